// round 11
// baseline (speedup 1.0000x reference)
#include <cuda_runtime.h>
#include <cuda_bf16.h>
#include <math_constants.h>
#include <stdint.h>

#define BB 2
#define SS 2048
#define DD 1024
#define HH 16
#define DH 64
#define MM (BB*SS)
#define MSZ (BB*SS*DD)
#define LOG2E 1.4426950408889634f

typedef __nv_bfloat16 bf16;
typedef __nv_bfloat162 bf162;

// ---------------------------------------------------------------------------
// Device scratch (bf16)
// ---------------------------------------------------------------------------
__device__ bf16 g_xb[MSZ];
__device__ bf16 g_yb[MSZ];
__device__ bf16 g_WqT[DD*DD];
__device__ bf16 g_WkT[DD*DD];
__device__ bf16 g_WvT[DD*DD];
__device__ bf16 g_WoxT[DD*DD];
__device__ bf16 g_WoyT[DD*DD];
__device__ bf16 g_qx[MSZ];
__device__ bf16 g_kx[MSZ];
__device__ bf16 g_qy[MSZ];
__device__ bf16 g_ky[MSZ];
__device__ bf16 g_vxT[MSZ];
__device__ bf16 g_vyT[MSZ];
__device__ bf16 g_a1[MSZ];
__device__ bf16 g_a2[MSZ];

// ---------------------------------------------------------------------------
// Helpers
// ---------------------------------------------------------------------------
__device__ __forceinline__ uint32_t s2u(const void* p) {
    return (uint32_t)__cvta_generic_to_shared(p);
}
#define CP16(dst, src) \
    asm volatile("cp.async.cg.shared.global [%0], [%1], 16;" :: "r"(dst), "l"(src))
#define CP_COMMIT() asm volatile("cp.async.commit_group;")
#define CP_WAIT(N)  asm volatile("cp.async.wait_group %0;" :: "n"(N))

__device__ __forceinline__ void mma_bf16(float c[4], const uint32_t a[4],
                                         uint32_t b0, uint32_t b1) {
    asm volatile(
        "mma.sync.aligned.m16n8k16.row.col.f32.bf16.bf16.f32 "
        "{%0,%1,%2,%3}, {%4,%5,%6,%7}, {%8,%9}, {%0,%1,%2,%3};\n"
        : "+f"(c[0]), "+f"(c[1]), "+f"(c[2]), "+f"(c[3])
        : "r"(a[0]), "r"(a[1]), "r"(a[2]), "r"(a[3]), "r"(b0), "r"(b1));
}

#define LDSM4(r, addr) \
    asm volatile("ldmatrix.sync.aligned.m8n8.x4.shared.b16 {%0,%1,%2,%3}, [%4];" \
                 : "=r"((r)[0]), "=r"((r)[1]), "=r"((r)[2]), "=r"((r)[3]) \
                 : "r"(addr))

__device__ __forceinline__ uint32_t pack2(float lo, float hi) {
    bf162 h = __floats2bfloat162_rn(lo, hi);
    return *reinterpret_cast<uint32_t*>(&h);
}

// ---------------------------------------------------------------------------
// Conversion kernels
// ---------------------------------------------------------------------------
__global__ void convxy(const float* __restrict__ x, const float* __restrict__ y,
                       bf16* __restrict__ xb, bf16* __restrict__ yb)
{
    const size_t i = ((size_t)blockIdx.x * 256 + threadIdx.x) * 4;
    const float* s = blockIdx.y ? y : x;
    bf16* d = blockIdx.y ? yb : xb;
    float4 v = *(const float4*)(s + i);
    uint2 w;
    w.x = pack2(v.x, v.y);
    w.y = pack2(v.z, v.w);
    *(uint2*)(d + i) = w;
}

// transpose + convert: WT[n][k] = bf16(W[k][n])
__global__ void wconv(const float* __restrict__ Wq, const float* __restrict__ Wk,
                      const float* __restrict__ Wv, const float* __restrict__ Wox,
                      const float* __restrict__ Woy,
                      bf16* WqT, bf16* WkT, bf16* WvT, bf16* WoxT, bf16* WoyT)
{
    __shared__ float t[32][33];
    const int z = blockIdx.z;
    const float* W = (z == 0) ? Wq : (z == 1) ? Wk : (z == 2) ? Wv : (z == 3) ? Wox : Woy;
    bf16* WT = (z == 0) ? WqT : (z == 1) ? WkT : (z == 2) ? WvT : (z == 3) ? WoxT : WoyT;
    const int k0 = blockIdx.y * 32, n0 = blockIdx.x * 32;
    const int tid = threadIdx.x;
    const int r = tid >> 3, c4 = (tid & 7) * 4;
    float4 v = *(const float4*)(W + (size_t)(k0 + r) * DD + n0 + c4);
    t[r][c4] = v.x; t[r][c4 + 1] = v.y; t[r][c4 + 2] = v.z; t[r][c4 + 3] = v.w;
    __syncthreads();
    uint2 w;
    w.x = pack2(t[c4][r], t[c4 + 1][r]);
    w.y = pack2(t[c4 + 2][r], t[c4 + 3][r]);
    *(uint2*)(WT + (size_t)(n0 + r) * DD + k0 + c4) = w;
}

// ---------------------------------------------------------------------------
// bf16 GEMM core: C[128,128] tile of A[.,1024](bf16,[m][k]) @ WT(bf16,[n][k])
// 256 thr / 8 warps (4m x 2n, warp tile 32x64). cp.async 4-stage, k-tile 32.
// Fragment loads via ldmatrix.x4. Optional transposed-V output (CT).
// ---------------------------------------------------------------------------
#define KT 32
#define SR 40                      // smem row stride (elements)
#define TSTG (128*SR)              // elements per (A|B) stage
#define GSTG 4
#define GEMM_SMEM_BYTES (GSTG*2*TSTG*2)   // 81920

__device__ __forceinline__ void gemm_core(
    const bf16* __restrict__ A, const bf16* __restrict__ WT,
    const float* __restrict__ bias, const float* __restrict__ res,
    float* __restrict__ Cf, bf16* __restrict__ Cb, bf16* __restrict__ CT,
    int row0, int col0, char* smraw)
{
    bf16* As = (bf16*)smraw;
    bf16* Bs = As + GSTG * TSTG;

    const int tid = threadIdx.x;
    const int lane = tid & 31;
    const int warp = tid >> 5;
    const int m_base = (warp >> 1) * 32;
    const int n_base = (warp & 1) * 64;
    const int tq = lane >> 2;
    const int tr = lane & 3;

    // ldmatrix lane-address constants (byte offsets into stage)
    const int sel = lane >> 3, rin = lane & 7;
    const int aC0 = ((m_base + (sel & 1) * 8 + rin) * SR + (sel >> 1) * 8) * 2;
    const int aC1 = aC0 + 16 * SR * 2;
    const int bC  = ((n_base + (sel >> 1) * 8 + rin) * SR + (sel & 1) * 8) * 2;

    auto prefetch = [&](int kt) {
        const int stg = kt & (GSTG - 1);
        const int k0 = kt * KT;
        bf16* as = As + stg * TSTG;
        bf16* bs = Bs + stg * TSTG;
#pragma unroll
        for (int i = 0; i < 4; i++) {
            const int c = tid + i * 256;           // 0..1023
            const int r = (c >> 2) & 127;
            const int jc = (c & 3) * 8;
            if (c < 512) {
                CP16(s2u(as + r * SR + jc), A + (size_t)(row0 + r) * DD + k0 + jc);
            } else {
                CP16(s2u(bs + r * SR + jc), WT + (size_t)(col0 + r) * DD + k0 + jc);
            }
        }
        CP_COMMIT();
    };

    float acc[2][8][4];
#pragma unroll
    for (int mt = 0; mt < 2; mt++)
#pragma unroll
        for (int nt = 0; nt < 8; nt++)
#pragma unroll
            for (int i = 0; i < 4; i++) acc[mt][nt][i] = 0.f;

    const int NK = DD / KT;  // 32
    prefetch(0); prefetch(1); prefetch(2);

    for (int kt = 0; kt < NK; kt++) {
        if (kt < NK - 2) { CP_WAIT(2); } else { CP_WAIT(0); }
        __syncthreads();
        if (kt + 3 < NK) prefetch(kt + 3);

        const int stg = kt & (GSTG - 1);
        const uint32_t asu = s2u(As + stg * TSTG);
        const uint32_t bsu = s2u(Bs + stg * TSTG);
#pragma unroll
        for (int ks = 0; ks < 2; ks++) {
            const int kb = ks * 32;   // byte offset of 16-elem k block
            uint32_t a0[4], a1[4];
            LDSM4(a0, asu + aC0 + kb);
            LDSM4(a1, asu + aC1 + kb);
#pragma unroll
            for (int np = 0; np < 4; np++) {
                uint32_t bfr[4];
                LDSM4(bfr, bsu + bC + np * (16 * SR * 2) + kb);
                mma_bf16(acc[0][2 * np],     a0, bfr[0], bfr[1]);
                mma_bf16(acc[0][2 * np + 1], a0, bfr[2], bfr[3]);
                mma_bf16(acc[1][2 * np],     a1, bfr[0], bfr[1]);
                mma_bf16(acc[1][2 * np + 1], a1, bfr[2], bfr[3]);
            }
        }
    }

    if (CT) {
        // ---- transposed-V epilogue: stage in smem, write vT[bh][dh][s] ----
        __syncthreads();                        // all warps done with stage smem
        bf16* Se = (bf16*)smraw;                // [128][136]
#pragma unroll
        for (int mt = 0; mt < 2; mt++) {
            const int m = m_base + mt * 16 + tq;
#pragma unroll
            for (int nt = 0; nt < 8; nt++) {
                const int c = n_base + nt * 8 + 2 * tr;
                *(uint32_t*)(Se + m * 136 + c) = pack2(acc[mt][nt][0], acc[mt][nt][1]);
                *(uint32_t*)(Se + (m + 8) * 136 + c) = pack2(acc[mt][nt][2], acc[mt][nt][3]);
            }
        }
        __syncthreads();
        const int bb = row0 >> 11;
        const int s_base = row0 & 2047;
#pragma unroll
        for (int ii = 0; ii < 8; ii++) {
            const int i = tid + ii * 256;       // 0..2047
            const int dh_l = i & 127;
            const int sc = (i >> 7) * 8;
            bf162 p0, p1, p2, p3;
            p0.x = Se[(sc + 0) * 136 + dh_l]; p0.y = Se[(sc + 1) * 136 + dh_l];
            p1.x = Se[(sc + 2) * 136 + dh_l]; p1.y = Se[(sc + 3) * 136 + dh_l];
            p2.x = Se[(sc + 4) * 136 + dh_l]; p2.y = Se[(sc + 5) * 136 + dh_l];
            p3.x = Se[(sc + 6) * 136 + dh_l]; p3.y = Se[(sc + 7) * 136 + dh_l];
            uint4 w;
            w.x = *reinterpret_cast<uint32_t*>(&p0);
            w.y = *reinterpret_cast<uint32_t*>(&p1);
            w.z = *reinterpret_cast<uint32_t*>(&p2);
            w.w = *reinterpret_cast<uint32_t*>(&p3);
            const int cg = col0 + dh_l;
            const int hh = cg >> 6, dh = cg & 63;
            *(uint4*)(CT + ((size_t)((bb * 16 + hh) * 64 + dh)) * SS + s_base + sc) = w;
        }
        return;
    }

    // ---- standard epilogue ----
#pragma unroll
    for (int mt = 0; mt < 2; mt++) {
        const int r0 = row0 + m_base + mt * 16 + tq;
#pragma unroll
        for (int nt = 0; nt < 8; nt++) {
            const int c = col0 + n_base + nt * 8 + 2 * tr;
            float v0 = acc[mt][nt][0], v1 = acc[mt][nt][1];
            float v2 = acc[mt][nt][2], v3 = acc[mt][nt][3];
            if (bias) {
                v0 += bias[c]; v1 += bias[c + 1];
                v2 += bias[c]; v3 += bias[c + 1];
            }
            if (res) {
                v0 += res[(size_t)r0 * DD + c];
                v1 += res[(size_t)r0 * DD + c + 1];
                v2 += res[(size_t)(r0 + 8) * DD + c];
                v3 += res[(size_t)(r0 + 8) * DD + c + 1];
            }
            if (Cb) {
                *(uint32_t*)(Cb + (size_t)r0 * DD + c) = pack2(v0, v1);
                *(uint32_t*)(Cb + (size_t)(r0 + 8) * DD + c) = pack2(v2, v3);
            } else {
                Cf[(size_t)r0 * DD + c] = v0;
                Cf[(size_t)r0 * DD + c + 1] = v1;
                Cf[(size_t)(r0 + 8) * DD + c] = v2;
                Cf[(size_t)(r0 + 8) * DD + c + 1] = v3;
            }
        }
    }
}

// All 6 input projections. Rows 0..4095 = x, 4096..8191 = y.
// z=2 (V) writes directly into transposed layout vT[b][h][dh][s].
__global__ __launch_bounds__(256, 2) void proj_kernel(
    const bf16* __restrict__ xb, const bf16* __restrict__ yb,
    const bf16* __restrict__ WqT, const bf16* __restrict__ WkT,
    const bf16* __restrict__ WvT,
    bf16* __restrict__ qx, bf16* __restrict__ kx,
    bf16* __restrict__ qy, bf16* __restrict__ ky,
    bf16* __restrict__ vxT, bf16* __restrict__ vyT)
{
    extern __shared__ char sm[];
    const int z = blockIdx.z;
    const int row0g = blockIdx.y * 128;
    const bool isx = (row0g < MM);
    const int row0 = isx ? row0g : row0g - MM;
    const bf16* A = isx ? xb : yb;
    const bf16* W = (z == 0) ? WqT : (z == 1) ? WkT : WvT;
    if (z == 2) {
        gemm_core(A, W, nullptr, nullptr, nullptr, nullptr,
                  isx ? vxT : vyT, row0, blockIdx.x * 128, sm);
    } else {
        bf16* C = (z == 0) ? (isx ? qy : qx) : (isx ? kx : ky);  // q cross-wired
        gemm_core(A, W, nullptr, nullptr, nullptr, C, nullptr,
                  row0, blockIdx.x * 128, sm);
    }
}

__global__ __launch_bounds__(256, 2) void out_kernel(
    const bf16* __restrict__ a1, const bf16* __restrict__ a2,
    const bf16* __restrict__ WoxT, const bf16* __restrict__ WoyT,
    const float* __restrict__ box, const float* __restrict__ boy,
    const float* __restrict__ x, const float* __restrict__ y,
    float* __restrict__ out)
{
    extern __shared__ char sm[];
    const int z = blockIdx.z;
    gemm_core(z ? a2 : a1, z ? WoyT : WoxT, z ? boy : box, z ? y : x,
              out + (size_t)z * MSZ, nullptr, nullptr,
              blockIdx.y * 128, blockIdx.x * 128, sm);
}

// ---------------------------------------------------------------------------
// Fused dual-stream flash attention: 512 threads / 16 warps.
// Warp w = (m-tile w>>1, role w&1). Scores: each warp does its n-half of
// the 128 key columns. PV: role 0 -> P@Vx, role 1 -> P@Vy (full 64 dh).
// Static softmax (bounded scores), P aliases the retired K tile.
// ---------------------------------------------------------------------------
#define AST 136                      // row stride (elems) for Q, K, V, P
#define JT 128                       // keys per iteration
#define QE (128*AST)
#define KPE (JT*AST)
#define VE (64*AST)
#define STAGEE (KPE + 2*VE)
#define LSUM_OFF ((QE + 2*STAGEE)*2)             // byte offset of Lsum
#define ATTN_SMEM_BYTES (LSUM_OFF + 128*2*4)     // 175104

__global__ __launch_bounds__(512, 1) void attn_tc(
    const bf16* __restrict__ qx, const bf16* __restrict__ kx, const bf16* __restrict__ vxT,
    const bf16* __restrict__ qy, const bf16* __restrict__ ky, const bf16* __restrict__ vyT,
    bf16* __restrict__ a1o, bf16* __restrict__ a2o)
{
    extern __shared__ char shraw[];
    bf16* Qs = (bf16*)shraw;
    float* Lsum = (float*)(shraw + LSUM_OFF);   // [128][2]

    const int tid = threadIdx.x;
    const int lane = tid & 31;
    const int warp = tid >> 5;      // 0..15
    const int mt = warp >> 1;       // 0..7
    const int st = warp & 1;        // 0: x-stream / cols 0..63; 1: y / 64..127
    const int tq = lane >> 2;
    const int tr = lane & 3;
    const int m0 = mt * 16;

    // ldmatrix lane constants (byte offsets)
    const int sel = lane >> 3, rin = lane & 7;
    const int aC = ((m0 + (sel & 1) * 8 + rin) * AST + (sel >> 1) * 8) * 2;  // A (Q or P)
    const int bC = (((sel >> 1) * 8 + rin) * AST + (sel & 1) * 8) * 2;       // B (K or V)
    const int bCs = bC + st * 64 * AST * 2;      // score B: key rows offset st*64

    const int bh = blockIdx.y;
    const int b = bh >> 4;
    const int h = bh & 15;
    const int q0 = blockIdx.x * 128;
    const size_t base = ((size_t)b * SS) * DD + (size_t)h * DH;
    const size_t vtb = (size_t)bh * DH * SS;

    auto kv_prefetch = [&](int j0, int stg) {
        bf16* Kb = Qs + QE + stg * STAGEE;
        bf16* Vxs = Kb + KPE;
        bf16* Vys = Vxs + VE;
#pragma unroll
        for (int i = 0; i < 8; i++) {
            const int c = tid + i * 512;   // 0..4095
            if (c < 2048) {
                const int row = c >> 4;
                const int half = (c >> 3) & 1;
                const int j = c & 7;
                const bf16* src = (half ? ky : kx) + base + (size_t)(j0 + row) * DD + j * 8;
                CP16(s2u(Kb + row * AST + half * 64 + j * 8), src);
            } else {
                const int c2 = c - 2048;
                const int t = c2 >> 10;
                const int r = (c2 >> 4) & 63;
                const int j = c2 & 15;
                const bf16* src = (t ? vyT : vxT) + vtb + (size_t)r * SS + j0 + j * 8;
                CP16(s2u((t ? Vys : Vxs) + r * AST + j * 8), src);
            }
        }
        CP_COMMIT();
    };

    // prologue: Q (own group) + stage 0
#pragma unroll
    for (int i = 0; i < 4; i++) {
        const int c = tid + i * 512;   // 0..2047
        const int row = c >> 4;
        const int half = (c >> 3) & 1;
        const int j = c & 7;
        const bf16* src = (half ? qy : qx) + base + (size_t)(q0 + row) * DD + j * 8;
        CP16(s2u(Qs + row * AST + half * 64 + j * 8), src);
    }
    CP_COMMIT();
    kv_prefetch(0, 0);

    const uint32_t qsu = s2u(Qs);

    float lr0 = 0.f, lr1 = 0.f;    // lane-private partial row sums (own n-half)
    float acc[8][4];               // 16 x 64 output tile for stream st
#pragma unroll
    for (int nt = 0; nt < 8; nt++)
#pragma unroll
        for (int i = 0; i < 4; i++) acc[nt][i] = 0.f;

    const float SC2 = LOG2E / 16.0f;

    for (int jn = 0; jn < SS / JT; jn++) {
        CP_WAIT(0);
        __syncthreads();
        if (jn + 1 < SS / JT) kv_prefetch((jn + 1) * JT, (jn + 1) & 1);

        bf16* Kb = Qs + QE + (jn & 1) * STAGEE;
        const uint32_t ksu = s2u(Kb);
        const uint32_t vsu = st ? s2u(Kb + KPE + VE) : s2u(Kb + KPE);
        bf16* Ps = Kb;   // alias after scores
        const uint32_t psu = ksu;

        // ---- scores: S[16 x 64] (own n-half) over concat k=128 ----
        float s[8][4];
#pragma unroll
        for (int nt = 0; nt < 8; nt++)
#pragma unroll
            for (int i = 0; i < 4; i++) s[nt][i] = 0.f;

#pragma unroll
        for (int k0 = 0; k0 < 128; k0 += 16) {
            const int kb = k0 * 2;
            uint32_t a[4];
            LDSM4(a, qsu + aC + kb);
#pragma unroll
            for (int np = 0; np < 4; np++) {
                uint32_t bfr[4];
                LDSM4(bfr, ksu + bCs + np * (16 * AST * 2) + kb);
                mma_bf16(s[2 * np],     a, bfr[0], bfr[1]);
                mma_bf16(s[2 * np + 1], a, bfr[2], bfr[3]);
            }
        }

        __syncthreads();   // K reads done before P overwrites the tile

        // ---- static softmax on own half: P = exp(s/16) ----
        const int pr0 = (m0 + tq) * AST + st * 64;
        const int pr1 = (m0 + tq + 8) * AST + st * 64;
#pragma unroll
        for (int nt = 0; nt < 8; nt++) {
            const int c = nt * 8 + 2 * tr;
            const float p0 = exp2f(s[nt][0] * SC2);
            const float p1 = exp2f(s[nt][1] * SC2);
            const float p2 = exp2f(s[nt][2] * SC2);
            const float p3 = exp2f(s[nt][3] * SC2);
            bf162 h01 = __floats2bfloat162_rn(p0, p1);
            bf162 h23 = __floats2bfloat162_rn(p2, p3);
            // sum the bf16-rounded values so l matches what PV consumes
            lr0 += __low2float(h01) + __high2float(h01);
            lr1 += __low2float(h23) + __high2float(h23);
            *(uint32_t*)(Ps + pr0 + c) = *reinterpret_cast<uint32_t*>(&h01);
            *(uint32_t*)(Ps + pr1 + c) = *reinterpret_cast<uint32_t*>(&h23);
        }
        __syncthreads();   // partner warp's P half must be visible

        // ---- PV for stream st: acc += P @ V^T (k = 128 keys, 64 dh) ----
#pragma unroll
        for (int k0 = 0; k0 < 128; k0 += 16) {
            const int kb = k0 * 2;
            uint32_t a[4];
            LDSM4(a, psu + aC + kb);
#pragma unroll
            for (int np = 0; np < 4; np++) {
                uint32_t bv[4];
                LDSM4(bv, vsu + bC + np * (16 * AST * 2) + kb);
                mma_bf16(acc[2 * np],     a, bv[0], bv[1]);
                mma_bf16(acc[2 * np + 1], a, bv[2], bv[3]);
            }
        }
    }

    // ---- l: reduce 4 lanes, exchange halves via smem ----
    lr0 += __shfl_xor_sync(0xffffffffu, lr0, 1);
    lr0 += __shfl_xor_sync(0xffffffffu, lr0, 2);
    lr1 += __shfl_xor_sync(0xffffffffu, lr1, 1);
    lr1 += __shfl_xor_sync(0xffffffffu, lr1, 2);
    if (tr == 0) {
        Lsum[(m0 + tq) * 2 + st] = lr0;
        Lsum[(m0 + tq + 8) * 2 + st] = lr1;
    }
    __syncthreads();
    const float inv0 = 1.0f / (Lsum[(m0 + tq) * 2] + Lsum[(m0 + tq) * 2 + 1]);
    const float inv1 = 1.0f / (Lsum[(m0 + tq + 8) * 2] + Lsum[(m0 + tq + 8) * 2 + 1]);

    // ---- normalize + write bf16 (stream st) ----
    bf16* ao = st ? a2o : a1o;
    const size_t r0g = base + (size_t)(q0 + m0 + tq) * DD;
    const size_t r1g = base + (size_t)(q0 + m0 + tq + 8) * DD;
#pragma unroll
    for (int nt = 0; nt < 8; nt++) {
        const int c = nt * 8 + 2 * tr;
        *(uint32_t*)(ao + r0g + c) = pack2(acc[nt][0] * inv0, acc[nt][1] * inv0);
        *(uint32_t*)(ao + r1g + c) = pack2(acc[nt][2] * inv1, acc[nt][3] * inv1);
    }
}

// ---------------------------------------------------------------------------
// Launch
// ---------------------------------------------------------------------------
extern "C" void kernel_launch(void* const* d_in, const int* in_sizes, int n_in,
                              void* d_out, int out_size)
{
    const float* x   = (const float*)d_in[0];
    const float* y   = (const float*)d_in[1];
    const float* Wq  = (const float*)d_in[2];
    const float* Wk  = (const float*)d_in[3];
    const float* Wv  = (const float*)d_in[4];
    const float* Wox = (const float*)d_in[5];
    const float* box = (const float*)d_in[6];
    const float* Woy = (const float*)d_in[7];
    const float* boy = (const float*)d_in[8];
    float* out = (float*)d_out;

    void* p;
    bf16 *xb, *yb, *WqT, *WkT, *WvT, *WoxT, *WoyT;
    bf16 *qx, *kx, *qy, *ky, *vxT, *vyT, *a1, *a2;
    cudaGetSymbolAddress(&p, g_xb);  xb  = (bf16*)p;
    cudaGetSymbolAddress(&p, g_yb);  yb  = (bf16*)p;
    cudaGetSymbolAddress(&p, g_WqT); WqT = (bf16*)p;
    cudaGetSymbolAddress(&p, g_WkT); WkT = (bf16*)p;
    cudaGetSymbolAddress(&p, g_WvT); WvT = (bf16*)p;
    cudaGetSymbolAddress(&p, g_WoxT); WoxT = (bf16*)p;
    cudaGetSymbolAddress(&p, g_WoyT); WoyT = (bf16*)p;
    cudaGetSymbolAddress(&p, g_qx);  qx = (bf16*)p;
    cudaGetSymbolAddress(&p, g_kx);  kx = (bf16*)p;
    cudaGetSymbolAddress(&p, g_qy);  qy = (bf16*)p;
    cudaGetSymbolAddress(&p, g_ky);  ky = (bf16*)p;
    cudaGetSymbolAddress(&p, g_vxT); vxT = (bf16*)p;
    cudaGetSymbolAddress(&p, g_vyT); vyT = (bf16*)p;
    cudaGetSymbolAddress(&p, g_a1);  a1 = (bf16*)p;
    cudaGetSymbolAddress(&p, g_a2);  a2 = (bf16*)p;

    cudaFuncSetAttribute(proj_kernel, cudaFuncAttributeMaxDynamicSharedMemorySize,
                         GEMM_SMEM_BYTES);
    cudaFuncSetAttribute(out_kernel, cudaFuncAttributeMaxDynamicSharedMemorySize,
                         GEMM_SMEM_BYTES);
    cudaFuncSetAttribute(attn_tc, cudaFuncAttributeMaxDynamicSharedMemorySize,
                         ATTN_SMEM_BYTES);

    convxy<<<dim3(MSZ / 1024, 2), 256>>>(x, y, xb, yb);
    wconv<<<dim3(32, 32, 5), 256>>>(Wq, Wk, Wv, Wox, Woy, WqT, WkT, WvT, WoxT, WoyT);

    proj_kernel<<<dim3(DD / 128, 2 * MM / 128, 3), 256, GEMM_SMEM_BYTES>>>(
        xb, yb, WqT, WkT, WvT, qx, kx, qy, ky, vxT, vyT);

    attn_tc<<<dim3(SS / 128, BB * HH), 512, ATTN_SMEM_BYTES>>>(
        qx, kx, vxT, qy, ky, vyT, a1, a2);

    out_kernel<<<dim3(DD / 128, MM / 128, 2), 256, GEMM_SMEM_BYTES>>>(
        a1, a2, WoxT, WoyT, box, boy, x, y, out);
}

// round 12
// speedup vs baseline: 1.0408x; 1.0408x over previous
#include <cuda_runtime.h>
#include <cuda_bf16.h>
#include <math_constants.h>
#include <stdint.h>

#define BB 2
#define SS 2048
#define DD 1024
#define HH 16
#define DH 64
#define MM (BB*SS)
#define MSZ (BB*SS*DD)
#define LOG2E 1.4426950408889634f

typedef __nv_bfloat16 bf16;
typedef __nv_bfloat162 bf162;

// ---------------------------------------------------------------------------
// Device scratch (bf16)
// ---------------------------------------------------------------------------
__device__ bf16 g_xb[MSZ];
__device__ bf16 g_yb[MSZ];
__device__ bf16 g_WqT[DD*DD];
__device__ bf16 g_WkT[DD*DD];
__device__ bf16 g_WvT[DD*DD];
__device__ bf16 g_WoxT[DD*DD];
__device__ bf16 g_WoyT[DD*DD];
__device__ bf16 g_qx[MSZ];
__device__ bf16 g_kx[MSZ];
__device__ bf16 g_qy[MSZ];
__device__ bf16 g_ky[MSZ];
__device__ bf16 g_vxT[MSZ];
__device__ bf16 g_vyT[MSZ];
__device__ bf16 g_a1[MSZ];
__device__ bf16 g_a2[MSZ];

// ---------------------------------------------------------------------------
// Helpers
// ---------------------------------------------------------------------------
__device__ __forceinline__ uint32_t s2u(const void* p) {
    return (uint32_t)__cvta_generic_to_shared(p);
}
#define CP16(dst, src) \
    asm volatile("cp.async.cg.shared.global [%0], [%1], 16;" :: "r"(dst), "l"(src))
#define CP_COMMIT() asm volatile("cp.async.commit_group;")
#define CP_WAIT(N)  asm volatile("cp.async.wait_group %0;" :: "n"(N))

__device__ __forceinline__ void mma_bf16(float c[4], const uint32_t a[4],
                                         uint32_t b0, uint32_t b1) {
    asm volatile(
        "mma.sync.aligned.m16n8k16.row.col.f32.bf16.bf16.f32 "
        "{%0,%1,%2,%3}, {%4,%5,%6,%7}, {%8,%9}, {%0,%1,%2,%3};\n"
        : "+f"(c[0]), "+f"(c[1]), "+f"(c[2]), "+f"(c[3])
        : "r"(a[0]), "r"(a[1]), "r"(a[2]), "r"(a[3]), "r"(b0), "r"(b1));
}

#define LDSM4(r, addr) \
    asm volatile("ldmatrix.sync.aligned.m8n8.x4.shared.b16 {%0,%1,%2,%3}, [%4];" \
                 : "=r"((r)[0]), "=r"((r)[1]), "=r"((r)[2]), "=r"((r)[3]) \
                 : "r"(addr))

__device__ __forceinline__ uint32_t pack2(float lo, float hi) {
    bf162 h = __floats2bfloat162_rn(lo, hi);
    return *reinterpret_cast<uint32_t*>(&h);
}

// ---------------------------------------------------------------------------
// Conversion kernels
// ---------------------------------------------------------------------------
__global__ void convxy(const float* __restrict__ x, const float* __restrict__ y,
                       bf16* __restrict__ xb, bf16* __restrict__ yb)
{
    const size_t i = ((size_t)blockIdx.x * 256 + threadIdx.x) * 4;
    const float* s = blockIdx.y ? y : x;
    bf16* d = blockIdx.y ? yb : xb;
    float4 v = *(const float4*)(s + i);
    uint2 w;
    w.x = pack2(v.x, v.y);
    w.y = pack2(v.z, v.w);
    *(uint2*)(d + i) = w;
}

// transpose + convert: WT[n][k] = bf16(W[k][n])
__global__ void wconv(const float* __restrict__ Wq, const float* __restrict__ Wk,
                      const float* __restrict__ Wv, const float* __restrict__ Wox,
                      const float* __restrict__ Woy,
                      bf16* WqT, bf16* WkT, bf16* WvT, bf16* WoxT, bf16* WoyT)
{
    __shared__ float t[32][33];
    const int z = blockIdx.z;
    const float* W = (z == 0) ? Wq : (z == 1) ? Wk : (z == 2) ? Wv : (z == 3) ? Wox : Woy;
    bf16* WT = (z == 0) ? WqT : (z == 1) ? WkT : (z == 2) ? WvT : (z == 3) ? WoxT : WoyT;
    const int k0 = blockIdx.y * 32, n0 = blockIdx.x * 32;
    const int tid = threadIdx.x;
    const int r = tid >> 3, c4 = (tid & 7) * 4;
    float4 v = *(const float4*)(W + (size_t)(k0 + r) * DD + n0 + c4);
    t[r][c4] = v.x; t[r][c4 + 1] = v.y; t[r][c4 + 2] = v.z; t[r][c4 + 3] = v.w;
    __syncthreads();
    uint2 w;
    w.x = pack2(t[c4][r], t[c4 + 1][r]);
    w.y = pack2(t[c4 + 2][r], t[c4 + 3][r]);
    *(uint2*)(WT + (size_t)(n0 + r) * DD + k0 + c4) = w;
}

// ---------------------------------------------------------------------------
// bf16 GEMM core: C[128,128] tile of A[.,1024](bf16,[m][k]) @ WT(bf16,[n][k])
// 256 thr / 8 warps (4m x 2n, warp tile 32x64). cp.async 4-stage, k-tile 32.
// Fragment loads via ldmatrix.x4. Optional transposed-V output (CT).
// ---------------------------------------------------------------------------
#define KT 32
#define SR 40                      // smem row stride (elements)
#define TSTG (128*SR)              // elements per (A|B) stage
#define GSTG 4
#define GEMM_SMEM_BYTES (GSTG*2*TSTG*2)   // 81920

__device__ __forceinline__ void gemm_core(
    const bf16* __restrict__ A, const bf16* __restrict__ WT,
    const float* __restrict__ bias, const float* __restrict__ res,
    float* __restrict__ Cf, bf16* __restrict__ Cb, bf16* __restrict__ CT,
    int row0, int col0, char* smraw)
{
    bf16* As = (bf16*)smraw;
    bf16* Bs = As + GSTG * TSTG;

    const int tid = threadIdx.x;
    const int lane = tid & 31;
    const int warp = tid >> 5;
    const int m_base = (warp >> 1) * 32;
    const int n_base = (warp & 1) * 64;
    const int tq = lane >> 2;
    const int tr = lane & 3;

    // ldmatrix lane-address constants (byte offsets into stage)
    const int sel = lane >> 3, rin = lane & 7;
    const int aC0 = ((m_base + (sel & 1) * 8 + rin) * SR + (sel >> 1) * 8) * 2;
    const int aC1 = aC0 + 16 * SR * 2;
    const int bC  = ((n_base + (sel >> 1) * 8 + rin) * SR + (sel & 1) * 8) * 2;

    auto prefetch = [&](int kt) {
        const int stg = kt & (GSTG - 1);
        const int k0 = kt * KT;
        bf16* as = As + stg * TSTG;
        bf16* bs = Bs + stg * TSTG;
#pragma unroll
        for (int i = 0; i < 4; i++) {
            const int c = tid + i * 256;           // 0..1023
            const int r = (c >> 2) & 127;
            const int jc = (c & 3) * 8;
            if (c < 512) {
                CP16(s2u(as + r * SR + jc), A + (size_t)(row0 + r) * DD + k0 + jc);
            } else {
                CP16(s2u(bs + r * SR + jc), WT + (size_t)(col0 + r) * DD + k0 + jc);
            }
        }
        CP_COMMIT();
    };

    float acc[2][8][4];
#pragma unroll
    for (int mt = 0; mt < 2; mt++)
#pragma unroll
        for (int nt = 0; nt < 8; nt++)
#pragma unroll
            for (int i = 0; i < 4; i++) acc[mt][nt][i] = 0.f;

    const int NK = DD / KT;  // 32
    prefetch(0); prefetch(1); prefetch(2);

    for (int kt = 0; kt < NK; kt++) {
        if (kt < NK - 2) { CP_WAIT(2); } else { CP_WAIT(0); }
        __syncthreads();
        if (kt + 3 < NK) prefetch(kt + 3);

        const int stg = kt & (GSTG - 1);
        const uint32_t asu = s2u(As + stg * TSTG);
        const uint32_t bsu = s2u(Bs + stg * TSTG);
#pragma unroll
        for (int ks = 0; ks < 2; ks++) {
            const int kb = ks * 32;   // byte offset of 16-elem k block
            uint32_t a0[4], a1[4];
            LDSM4(a0, asu + aC0 + kb);
            LDSM4(a1, asu + aC1 + kb);
#pragma unroll
            for (int np = 0; np < 4; np++) {
                uint32_t bfr[4];
                LDSM4(bfr, bsu + bC + np * (16 * SR * 2) + kb);
                mma_bf16(acc[0][2 * np],     a0, bfr[0], bfr[1]);
                mma_bf16(acc[0][2 * np + 1], a0, bfr[2], bfr[3]);
                mma_bf16(acc[1][2 * np],     a1, bfr[0], bfr[1]);
                mma_bf16(acc[1][2 * np + 1], a1, bfr[2], bfr[3]);
            }
        }
    }

    if (CT) {
        // ---- transposed-V epilogue: stage in smem, write vT[bh][dh][s] ----
        __syncthreads();                        // all warps done with stage smem
        bf16* Se = (bf16*)smraw;                // [128][136]
#pragma unroll
        for (int mt = 0; mt < 2; mt++) {
            const int m = m_base + mt * 16 + tq;
#pragma unroll
            for (int nt = 0; nt < 8; nt++) {
                const int c = n_base + nt * 8 + 2 * tr;
                *(uint32_t*)(Se + m * 136 + c) = pack2(acc[mt][nt][0], acc[mt][nt][1]);
                *(uint32_t*)(Se + (m + 8) * 136 + c) = pack2(acc[mt][nt][2], acc[mt][nt][3]);
            }
        }
        __syncthreads();
        const int bb = row0 >> 11;
        const int s_base = row0 & 2047;
#pragma unroll
        for (int ii = 0; ii < 8; ii++) {
            const int i = tid + ii * 256;       // 0..2047
            const int dh_l = i & 127;
            const int sc = (i >> 7) * 8;
            bf162 p0, p1, p2, p3;
            p0.x = Se[(sc + 0) * 136 + dh_l]; p0.y = Se[(sc + 1) * 136 + dh_l];
            p1.x = Se[(sc + 2) * 136 + dh_l]; p1.y = Se[(sc + 3) * 136 + dh_l];
            p2.x = Se[(sc + 4) * 136 + dh_l]; p2.y = Se[(sc + 5) * 136 + dh_l];
            p3.x = Se[(sc + 6) * 136 + dh_l]; p3.y = Se[(sc + 7) * 136 + dh_l];
            uint4 w;
            w.x = *reinterpret_cast<uint32_t*>(&p0);
            w.y = *reinterpret_cast<uint32_t*>(&p1);
            w.z = *reinterpret_cast<uint32_t*>(&p2);
            w.w = *reinterpret_cast<uint32_t*>(&p3);
            const int cg = col0 + dh_l;
            const int hh = cg >> 6, dh = cg & 63;
            *(uint4*)(CT + ((size_t)((bb * 16 + hh) * 64 + dh)) * SS + s_base + sc) = w;
        }
        return;
    }

    // ---- standard epilogue ----
#pragma unroll
    for (int mt = 0; mt < 2; mt++) {
        const int r0 = row0 + m_base + mt * 16 + tq;
#pragma unroll
        for (int nt = 0; nt < 8; nt++) {
            const int c = col0 + n_base + nt * 8 + 2 * tr;
            float v0 = acc[mt][nt][0], v1 = acc[mt][nt][1];
            float v2 = acc[mt][nt][2], v3 = acc[mt][nt][3];
            if (bias) {
                v0 += bias[c]; v1 += bias[c + 1];
                v2 += bias[c]; v3 += bias[c + 1];
            }
            if (res) {
                v0 += res[(size_t)r0 * DD + c];
                v1 += res[(size_t)r0 * DD + c + 1];
                v2 += res[(size_t)(r0 + 8) * DD + c];
                v3 += res[(size_t)(r0 + 8) * DD + c + 1];
            }
            if (Cb) {
                *(uint32_t*)(Cb + (size_t)r0 * DD + c) = pack2(v0, v1);
                *(uint32_t*)(Cb + (size_t)(r0 + 8) * DD + c) = pack2(v2, v3);
            } else {
                Cf[(size_t)r0 * DD + c] = v0;
                Cf[(size_t)r0 * DD + c + 1] = v1;
                Cf[(size_t)(r0 + 8) * DD + c] = v2;
                Cf[(size_t)(r0 + 8) * DD + c + 1] = v3;
            }
        }
    }
}

// All 6 input projections. Rows 0..4095 = x, 4096..8191 = y.
// z=2 (V) writes directly into transposed layout vT[b][h][dh][s].
__global__ __launch_bounds__(256, 2) void proj_kernel(
    const bf16* __restrict__ xb, const bf16* __restrict__ yb,
    const bf16* __restrict__ WqT, const bf16* __restrict__ WkT,
    const bf16* __restrict__ WvT,
    bf16* __restrict__ qx, bf16* __restrict__ kx,
    bf16* __restrict__ qy, bf16* __restrict__ ky,
    bf16* __restrict__ vxT, bf16* __restrict__ vyT)
{
    extern __shared__ char sm[];
    const int z = blockIdx.z;
    const int row0g = blockIdx.y * 128;
    const bool isx = (row0g < MM);
    const int row0 = isx ? row0g : row0g - MM;
    const bf16* A = isx ? xb : yb;
    const bf16* W = (z == 0) ? WqT : (z == 1) ? WkT : WvT;
    if (z == 2) {
        gemm_core(A, W, nullptr, nullptr, nullptr, nullptr,
                  isx ? vxT : vyT, row0, blockIdx.x * 128, sm);
    } else {
        bf16* C = (z == 0) ? (isx ? qy : qx) : (isx ? kx : ky);  // q cross-wired
        gemm_core(A, W, nullptr, nullptr, nullptr, C, nullptr,
                  row0, blockIdx.x * 128, sm);
    }
}

__global__ __launch_bounds__(256, 2) void out_kernel(
    const bf16* __restrict__ a1, const bf16* __restrict__ a2,
    const bf16* __restrict__ WoxT, const bf16* __restrict__ WoyT,
    const float* __restrict__ box, const float* __restrict__ boy,
    const float* __restrict__ x, const float* __restrict__ y,
    float* __restrict__ out)
{
    extern __shared__ char sm[];
    const int z = blockIdx.z;
    gemm_core(z ? a2 : a1, z ? WoyT : WoxT, z ? boy : box, z ? y : x,
              out + (size_t)z * MSZ, nullptr, nullptr,
              blockIdx.y * 128, blockIdx.x * 128, sm);
}

// ---------------------------------------------------------------------------
// Fused dual-stream flash attention: 256 thr / 8 warps (R9 structure) with a
// DEDICATED P buffer — no K-alias, so the mid-iteration full barrier becomes
// a __syncwarp. One __syncthreads per j-iteration. Static softmax.
// ---------------------------------------------------------------------------
#define AST 136                      // row stride (elems) for Q, K, V, P
#define JT 128                       // keys per iteration
#define QE (128*AST)                 // 17408 elems
#define KPE (JT*AST)                 // 17408 elems (K tile)
#define VE (64*AST)                  // 8704 elems per V stream
#define STAGEE (KPE + 2*VE)          // 34816 elems
#define PE_OFF (QE + 2*STAGEE)       // P buffer offset (elems)
#define ATTN_SMEM_BYTES ((PE_OFF + 128*AST)*2)   // 208896

__global__ __launch_bounds__(256, 1) void attn_tc(
    const bf16* __restrict__ qx, const bf16* __restrict__ kx, const bf16* __restrict__ vxT,
    const bf16* __restrict__ qy, const bf16* __restrict__ ky, const bf16* __restrict__ vyT,
    bf16* __restrict__ a1o, bf16* __restrict__ a2o)
{
    extern __shared__ char shraw[];
    bf16* Qs = (bf16*)shraw;
    bf16* Ps = Qs + PE_OFF;          // dedicated P tile [128][AST]

    const int tid = threadIdx.x;
    const int lane = tid & 31;
    const int warp = tid >> 5;
    const int tq = lane >> 2;
    const int tr = lane & 3;
    const int m0 = warp * 16;

    // ldmatrix lane constants (byte offsets)
    const int sel = lane >> 3, rin = lane & 7;
    const int aC = ((m0 + (sel & 1) * 8 + rin) * AST + (sel >> 1) * 8) * 2;  // A (Q or P)
    const int bC = (((sel >> 1) * 8 + rin) * AST + (sel & 1) * 8) * 2;       // B (K or V)

    const int bh = blockIdx.y;
    const int b = bh >> 4;
    const int h = bh & 15;
    const int q0 = blockIdx.x * 128;
    const size_t base = ((size_t)b * SS) * DD + (size_t)h * DH;
    const size_t vtb = (size_t)bh * DH * SS;

    auto kv_prefetch = [&](int j0, int stg) {
        bf16* Kb = Qs + QE + stg * STAGEE;
        bf16* Vxs = Kb + KPE;
        bf16* Vys = Vxs + VE;
#pragma unroll
        for (int i = 0; i < 16; i++) {
            const int c = tid + i * 256;   // 0..4095
            if (c < 2048) {
                const int row = c >> 4;
                const int half = (c >> 3) & 1;
                const int j = c & 7;
                const bf16* src = (half ? ky : kx) + base + (size_t)(j0 + row) * DD + j * 8;
                CP16(s2u(Kb + row * AST + half * 64 + j * 8), src);
            } else {
                const int c2 = c - 2048;
                const int t = c2 >> 10;
                const int r = (c2 >> 4) & 63;
                const int j = c2 & 15;
                const bf16* src = (t ? vyT : vxT) + vtb + (size_t)r * SS + j0 + j * 8;
                CP16(s2u((t ? Vys : Vxs) + r * AST + j * 8), src);
            }
        }
        CP_COMMIT();
    };

    // prologue: Q (own group) + stage 0
#pragma unroll
    for (int i = 0; i < 8; i++) {
        const int c = tid + i * 256;
        const int row = c >> 4;
        const int half = (c >> 3) & 1;
        const int j = c & 7;
        const bf16* src = (half ? qy : qx) + base + (size_t)(q0 + row) * DD + j * 8;
        CP16(s2u(Qs + row * AST + half * 64 + j * 8), src);
    }
    CP_COMMIT();
    kv_prefetch(0, 0);

    const uint32_t qsu = s2u(Qs);
    const uint32_t psu = s2u(Ps);

    float lr0 = 0.f, lr1 = 0.f;    // lane-private partial row sums
    float acc1[8][4], acc2[8][4];
#pragma unroll
    for (int nt = 0; nt < 8; nt++)
#pragma unroll
        for (int i = 0; i < 4; i++) { acc1[nt][i] = 0.f; acc2[nt][i] = 0.f; }

    const float SC2 = LOG2E / 16.0f;

    for (int jn = 0; jn < SS / JT; jn++) {
        CP_WAIT(0);
        __syncthreads();
        if (jn + 1 < SS / JT) kv_prefetch((jn + 1) * JT, (jn + 1) & 1);

        bf16* Kb = Qs + QE + (jn & 1) * STAGEE;
        const uint32_t ksu = s2u(Kb);
        const uint32_t vxsu = s2u(Kb + KPE);
        const uint32_t vysu = s2u(Kb + KPE + VE);

        // ---- scores: S[16 x 128] over concat k=128 ----
        float s[16][4];
#pragma unroll
        for (int nt = 0; nt < 16; nt++)
#pragma unroll
            for (int i = 0; i < 4; i++) s[nt][i] = 0.f;

#pragma unroll
        for (int k0 = 0; k0 < 128; k0 += 16) {
            const int kb = k0 * 2;
            uint32_t a[4];
            LDSM4(a, qsu + aC + kb);
#pragma unroll
            for (int np = 0; np < 8; np++) {
                uint32_t bfr[4];
                LDSM4(bfr, ksu + bC + np * (16 * AST * 2) + kb);
                mma_bf16(s[2 * np],     a, bfr[0], bfr[1]);
                mma_bf16(s[2 * np + 1], a, bfr[2], bfr[3]);
            }
        }

        // ---- static softmax: P = exp(s/16); warp-private P rows ----
        const int pr0 = (m0 + tq) * AST;
        const int pr1 = (m0 + tq + 8) * AST;
#pragma unroll
        for (int nt = 0; nt < 16; nt++) {
            const int c = nt * 8 + 2 * tr;
            const float p0 = exp2f(s[nt][0] * SC2);
            const float p1 = exp2f(s[nt][1] * SC2);
            const float p2 = exp2f(s[nt][2] * SC2);
            const float p3 = exp2f(s[nt][3] * SC2);
            bf162 h01 = __floats2bfloat162_rn(p0, p1);
            bf162 h23 = __floats2bfloat162_rn(p2, p3);
            // sum the bf16-rounded values so l matches what PV consumes
            lr0 += __low2float(h01) + __high2float(h01);
            lr1 += __low2float(h23) + __high2float(h23);
            *(uint32_t*)(Ps + pr0 + c) = *reinterpret_cast<uint32_t*>(&h01);
            *(uint32_t*)(Ps + pr1 + c) = *reinterpret_cast<uint32_t*>(&h23);
        }
        __syncwarp();   // own-warp P visible to own-warp ldmatrix

        // ---- PV: acc1 += P@Vx^T, acc2 += P@Vy^T (k = 128 keys) ----
#pragma unroll
        for (int k0 = 0; k0 < 128; k0 += 16) {
            const int kb = k0 * 2;
            uint32_t a[4];
            LDSM4(a, psu + aC + kb);
#pragma unroll
            for (int np = 0; np < 4; np++) {
                uint32_t bx[4], by[4];
                LDSM4(bx, vxsu + bC + np * (16 * AST * 2) + kb);
                mma_bf16(acc1[2 * np],     a, bx[0], bx[1]);
                mma_bf16(acc1[2 * np + 1], a, bx[2], bx[3]);
                LDSM4(by, vysu + bC + np * (16 * AST * 2) + kb);
                mma_bf16(acc2[2 * np],     a, by[0], by[1]);
                mma_bf16(acc2[2 * np + 1], a, by[2], by[3]);
            }
        }
    }

    // ---- final l reduction across the 4 lanes sharing each row ----
    lr0 += __shfl_xor_sync(0xffffffffu, lr0, 1);
    lr0 += __shfl_xor_sync(0xffffffffu, lr0, 2);
    lr1 += __shfl_xor_sync(0xffffffffu, lr1, 1);
    lr1 += __shfl_xor_sync(0xffffffffu, lr1, 2);

    // ---- normalize + write bf16 ----
    const float inv0 = 1.0f / lr0;
    const float inv1 = 1.0f / lr1;
    const size_t r0g = base + (size_t)(q0 + m0 + tq) * DD;
    const size_t r1g = base + (size_t)(q0 + m0 + tq + 8) * DD;
#pragma unroll
    for (int nt = 0; nt < 8; nt++) {
        const int c = nt * 8 + 2 * tr;
        *(uint32_t*)(a1o + r0g + c) = pack2(acc1[nt][0] * inv0, acc1[nt][1] * inv0);
        *(uint32_t*)(a1o + r1g + c) = pack2(acc1[nt][2] * inv1, acc1[nt][3] * inv1);
        *(uint32_t*)(a2o + r0g + c) = pack2(acc2[nt][0] * inv0, acc2[nt][1] * inv0);
        *(uint32_t*)(a2o + r1g + c) = pack2(acc2[nt][2] * inv1, acc2[nt][3] * inv1);
    }
}

// ---------------------------------------------------------------------------
// Launch
// ---------------------------------------------------------------------------
extern "C" void kernel_launch(void* const* d_in, const int* in_sizes, int n_in,
                              void* d_out, int out_size)
{
    const float* x   = (const float*)d_in[0];
    const float* y   = (const float*)d_in[1];
    const float* Wq  = (const float*)d_in[2];
    const float* Wk  = (const float*)d_in[3];
    const float* Wv  = (const float*)d_in[4];
    const float* Wox = (const float*)d_in[5];
    const float* box = (const float*)d_in[6];
    const float* Woy = (const float*)d_in[7];
    const float* boy = (const float*)d_in[8];
    float* out = (float*)d_out;

    void* p;
    bf16 *xb, *yb, *WqT, *WkT, *WvT, *WoxT, *WoyT;
    bf16 *qx, *kx, *qy, *ky, *vxT, *vyT, *a1, *a2;
    cudaGetSymbolAddress(&p, g_xb);  xb  = (bf16*)p;
    cudaGetSymbolAddress(&p, g_yb);  yb  = (bf16*)p;
    cudaGetSymbolAddress(&p, g_WqT); WqT = (bf16*)p;
    cudaGetSymbolAddress(&p, g_WkT); WkT = (bf16*)p;
    cudaGetSymbolAddress(&p, g_WvT); WvT = (bf16*)p;
    cudaGetSymbolAddress(&p, g_WoxT); WoxT = (bf16*)p;
    cudaGetSymbolAddress(&p, g_WoyT); WoyT = (bf16*)p;
    cudaGetSymbolAddress(&p, g_qx);  qx = (bf16*)p;
    cudaGetSymbolAddress(&p, g_kx);  kx = (bf16*)p;
    cudaGetSymbolAddress(&p, g_qy);  qy = (bf16*)p;
    cudaGetSymbolAddress(&p, g_ky);  ky = (bf16*)p;
    cudaGetSymbolAddress(&p, g_vxT); vxT = (bf16*)p;
    cudaGetSymbolAddress(&p, g_vyT); vyT = (bf16*)p;
    cudaGetSymbolAddress(&p, g_a1);  a1 = (bf16*)p;
    cudaGetSymbolAddress(&p, g_a2);  a2 = (bf16*)p;

    cudaFuncSetAttribute(proj_kernel, cudaFuncAttributeMaxDynamicSharedMemorySize,
                         GEMM_SMEM_BYTES);
    cudaFuncSetAttribute(out_kernel, cudaFuncAttributeMaxDynamicSharedMemorySize,
                         GEMM_SMEM_BYTES);
    cudaFuncSetAttribute(attn_tc, cudaFuncAttributeMaxDynamicSharedMemorySize,
                         ATTN_SMEM_BYTES);

    convxy<<<dim3(MSZ / 1024, 2), 256>>>(x, y, xb, yb);
    wconv<<<dim3(32, 32, 5), 256>>>(Wq, Wk, Wv, Wox, Woy, WqT, WkT, WvT, WoxT, WoyT);

    proj_kernel<<<dim3(DD / 128, 2 * MM / 128, 3), 256, GEMM_SMEM_BYTES>>>(
        xb, yb, WqT, WkT, WvT, qx, kx, qy, ky, vxT, vyT);

    attn_tc<<<dim3(SS / 128, BB * HH), 256, ATTN_SMEM_BYTES>>>(
        qx, kx, vxT, qy, ky, vyT, a1, a2);

    out_kernel<<<dim3(DD / 128, MM / 128, 2), 256, GEMM_SMEM_BYTES>>>(
        a1, a2, WoxT, WoyT, box, boy, x, y, out);
}

// round 13
// speedup vs baseline: 1.0646x; 1.0229x over previous
#include <cuda_runtime.h>
#include <cuda_bf16.h>
#include <math_constants.h>
#include <stdint.h>

#define BB 2
#define SS 2048
#define DD 1024
#define HH 16
#define DH 64
#define MM (BB*SS)
#define MSZ (BB*SS*DD)
#define LOG2E 1.4426950408889634f

typedef __nv_bfloat16 bf16;
typedef __nv_bfloat162 bf162;

// ---------------------------------------------------------------------------
// Device scratch (bf16)
// ---------------------------------------------------------------------------
__device__ bf16 g_xb[MSZ];
__device__ bf16 g_yb[MSZ];
__device__ bf16 g_WqT[DD*DD];
__device__ bf16 g_WkT[DD*DD];
__device__ bf16 g_WvT[DD*DD];
__device__ bf16 g_WoxT[DD*DD];
__device__ bf16 g_WoyT[DD*DD];
__device__ bf16 g_qx[MSZ];
__device__ bf16 g_kx[MSZ];
__device__ bf16 g_qy[MSZ];
__device__ bf16 g_ky[MSZ];
__device__ bf16 g_vxT[MSZ];
__device__ bf16 g_vyT[MSZ];
__device__ bf16 g_a1[MSZ];
__device__ bf16 g_a2[MSZ];

// ---------------------------------------------------------------------------
// Helpers
// ---------------------------------------------------------------------------
__device__ __forceinline__ uint32_t s2u(const void* p) {
    return (uint32_t)__cvta_generic_to_shared(p);
}
#define CP16(dst, src) \
    asm volatile("cp.async.cg.shared.global [%0], [%1], 16;" :: "r"(dst), "l"(src))
#define CP_COMMIT() asm volatile("cp.async.commit_group;")
#define CP_WAIT(N)  asm volatile("cp.async.wait_group %0;" :: "n"(N))

__device__ __forceinline__ void mma_bf16(float c[4], const uint32_t a[4],
                                         uint32_t b0, uint32_t b1) {
    asm volatile(
        "mma.sync.aligned.m16n8k16.row.col.f32.bf16.bf16.f32 "
        "{%0,%1,%2,%3}, {%4,%5,%6,%7}, {%8,%9}, {%0,%1,%2,%3};\n"
        : "+f"(c[0]), "+f"(c[1]), "+f"(c[2]), "+f"(c[3])
        : "r"(a[0]), "r"(a[1]), "r"(a[2]), "r"(a[3]), "r"(b0), "r"(b1));
}

#define LDSM4(r, addr) \
    asm volatile("ldmatrix.sync.aligned.m8n8.x4.shared.b16 {%0,%1,%2,%3}, [%4];" \
                 : "=r"((r)[0]), "=r"((r)[1]), "=r"((r)[2]), "=r"((r)[3]) \
                 : "r"(addr))

__device__ __forceinline__ uint32_t pack2(float lo, float hi) {
    bf162 h = __floats2bfloat162_rn(lo, hi);
    return *reinterpret_cast<uint32_t*>(&h);
}

// ---------------------------------------------------------------------------
// Conversion kernels
// ---------------------------------------------------------------------------
__global__ void convxy(const float* __restrict__ x, const float* __restrict__ y,
                       bf16* __restrict__ xb, bf16* __restrict__ yb)
{
    const size_t i = ((size_t)blockIdx.x * 256 + threadIdx.x) * 4;
    const float* s = blockIdx.y ? y : x;
    bf16* d = blockIdx.y ? yb : xb;
    float4 v = *(const float4*)(s + i);
    uint2 w;
    w.x = pack2(v.x, v.y);
    w.y = pack2(v.z, v.w);
    *(uint2*)(d + i) = w;
}

// transpose + convert: WT[n][k] = bf16(W[k][n])
__global__ void wconv(const float* __restrict__ Wq, const float* __restrict__ Wk,
                      const float* __restrict__ Wv, const float* __restrict__ Wox,
                      const float* __restrict__ Woy,
                      bf16* WqT, bf16* WkT, bf16* WvT, bf16* WoxT, bf16* WoyT)
{
    __shared__ float t[32][33];
    const int z = blockIdx.z;
    const float* W = (z == 0) ? Wq : (z == 1) ? Wk : (z == 2) ? Wv : (z == 3) ? Wox : Woy;
    bf16* WT = (z == 0) ? WqT : (z == 1) ? WkT : (z == 2) ? WvT : (z == 3) ? WoxT : WoyT;
    const int k0 = blockIdx.y * 32, n0 = blockIdx.x * 32;
    const int tid = threadIdx.x;
    const int r = tid >> 3, c4 = (tid & 7) * 4;
    float4 v = *(const float4*)(W + (size_t)(k0 + r) * DD + n0 + c4);
    t[r][c4] = v.x; t[r][c4 + 1] = v.y; t[r][c4 + 2] = v.z; t[r][c4 + 3] = v.w;
    __syncthreads();
    uint2 w;
    w.x = pack2(t[c4][r], t[c4 + 1][r]);
    w.y = pack2(t[c4 + 2][r], t[c4 + 3][r]);
    *(uint2*)(WT + (size_t)(n0 + r) * DD + k0 + c4) = w;
}

// ---------------------------------------------------------------------------
// bf16 GEMM core: C[128,128] tile of A[.,1024](bf16,[m][k]) @ WT(bf16,[n][k])
// 256 thr / 8 warps (4m x 2n, warp tile 32x64). cp.async 4-stage, k-tile 32.
// Fragment loads via ldmatrix.x4. Optional transposed-V output (CT).
// ---------------------------------------------------------------------------
#define KT 32
#define SR 40                      // smem row stride (elements)
#define TSTG (128*SR)              // elements per (A|B) stage
#define GSTG 4
#define GEMM_SMEM_BYTES (GSTG*2*TSTG*2)   // 81920

__device__ __forceinline__ void gemm_core(
    const bf16* __restrict__ A, const bf16* __restrict__ WT,
    const float* __restrict__ bias, const float* __restrict__ res,
    float* __restrict__ Cf, bf16* __restrict__ Cb, bf16* __restrict__ CT,
    int row0, int col0, char* smraw)
{
    bf16* As = (bf16*)smraw;
    bf16* Bs = As + GSTG * TSTG;

    const int tid = threadIdx.x;
    const int lane = tid & 31;
    const int warp = tid >> 5;
    const int m_base = (warp >> 1) * 32;
    const int n_base = (warp & 1) * 64;
    const int tq = lane >> 2;
    const int tr = lane & 3;

    // ldmatrix lane-address constants (byte offsets into stage)
    const int sel = lane >> 3, rin = lane & 7;
    const int aC0 = ((m_base + (sel & 1) * 8 + rin) * SR + (sel >> 1) * 8) * 2;
    const int aC1 = aC0 + 16 * SR * 2;
    const int bC  = ((n_base + (sel >> 1) * 8 + rin) * SR + (sel & 1) * 8) * 2;

    auto prefetch = [&](int kt) {
        const int stg = kt & (GSTG - 1);
        const int k0 = kt * KT;
        bf16* as = As + stg * TSTG;
        bf16* bs = Bs + stg * TSTG;
#pragma unroll
        for (int i = 0; i < 4; i++) {
            const int c = tid + i * 256;           // 0..1023
            const int r = (c >> 2) & 127;
            const int jc = (c & 3) * 8;
            if (c < 512) {
                CP16(s2u(as + r * SR + jc), A + (size_t)(row0 + r) * DD + k0 + jc);
            } else {
                CP16(s2u(bs + r * SR + jc), WT + (size_t)(col0 + r) * DD + k0 + jc);
            }
        }
        CP_COMMIT();
    };

    float acc[2][8][4];
#pragma unroll
    for (int mt = 0; mt < 2; mt++)
#pragma unroll
        for (int nt = 0; nt < 8; nt++)
#pragma unroll
            for (int i = 0; i < 4; i++) acc[mt][nt][i] = 0.f;

    const int NK = DD / KT;  // 32
    prefetch(0); prefetch(1); prefetch(2);

    for (int kt = 0; kt < NK; kt++) {
        if (kt < NK - 2) { CP_WAIT(2); } else { CP_WAIT(0); }
        __syncthreads();
        if (kt + 3 < NK) prefetch(kt + 3);

        const int stg = kt & (GSTG - 1);
        const uint32_t asu = s2u(As + stg * TSTG);
        const uint32_t bsu = s2u(Bs + stg * TSTG);
#pragma unroll
        for (int ks = 0; ks < 2; ks++) {
            const int kb = ks * 32;   // byte offset of 16-elem k block
            uint32_t a0[4], a1[4];
            LDSM4(a0, asu + aC0 + kb);
            LDSM4(a1, asu + aC1 + kb);
#pragma unroll
            for (int np = 0; np < 4; np++) {
                uint32_t bfr[4];
                LDSM4(bfr, bsu + bC + np * (16 * SR * 2) + kb);
                mma_bf16(acc[0][2 * np],     a0, bfr[0], bfr[1]);
                mma_bf16(acc[0][2 * np + 1], a0, bfr[2], bfr[3]);
                mma_bf16(acc[1][2 * np],     a1, bfr[0], bfr[1]);
                mma_bf16(acc[1][2 * np + 1], a1, bfr[2], bfr[3]);
            }
        }
    }

    if (CT) {
        // ---- transposed-V epilogue: stage in smem, write vT[bh][dh][s] ----
        __syncthreads();                        // all warps done with stage smem
        bf16* Se = (bf16*)smraw;                // [128][136]
#pragma unroll
        for (int mt = 0; mt < 2; mt++) {
            const int m = m_base + mt * 16 + tq;
#pragma unroll
            for (int nt = 0; nt < 8; nt++) {
                const int c = n_base + nt * 8 + 2 * tr;
                *(uint32_t*)(Se + m * 136 + c) = pack2(acc[mt][nt][0], acc[mt][nt][1]);
                *(uint32_t*)(Se + (m + 8) * 136 + c) = pack2(acc[mt][nt][2], acc[mt][nt][3]);
            }
        }
        __syncthreads();
        const int bb = row0 >> 11;
        const int s_base = row0 & 2047;
#pragma unroll
        for (int ii = 0; ii < 8; ii++) {
            const int i = tid + ii * 256;       // 0..2047
            const int dh_l = i & 127;
            const int sc = (i >> 7) * 8;
            bf162 p0, p1, p2, p3;
            p0.x = Se[(sc + 0) * 136 + dh_l]; p0.y = Se[(sc + 1) * 136 + dh_l];
            p1.x = Se[(sc + 2) * 136 + dh_l]; p1.y = Se[(sc + 3) * 136 + dh_l];
            p2.x = Se[(sc + 4) * 136 + dh_l]; p2.y = Se[(sc + 5) * 136 + dh_l];
            p3.x = Se[(sc + 6) * 136 + dh_l]; p3.y = Se[(sc + 7) * 136 + dh_l];
            uint4 w;
            w.x = *reinterpret_cast<uint32_t*>(&p0);
            w.y = *reinterpret_cast<uint32_t*>(&p1);
            w.z = *reinterpret_cast<uint32_t*>(&p2);
            w.w = *reinterpret_cast<uint32_t*>(&p3);
            const int cg = col0 + dh_l;
            const int hh = cg >> 6, dh = cg & 63;
            *(uint4*)(CT + ((size_t)((bb * 16 + hh) * 64 + dh)) * SS + s_base + sc) = w;
        }
        return;
    }

    // ---- standard epilogue ----
#pragma unroll
    for (int mt = 0; mt < 2; mt++) {
        const int r0 = row0 + m_base + mt * 16 + tq;
#pragma unroll
        for (int nt = 0; nt < 8; nt++) {
            const int c = col0 + n_base + nt * 8 + 2 * tr;
            float v0 = acc[mt][nt][0], v1 = acc[mt][nt][1];
            float v2 = acc[mt][nt][2], v3 = acc[mt][nt][3];
            if (bias) {
                v0 += bias[c]; v1 += bias[c + 1];
                v2 += bias[c]; v3 += bias[c + 1];
            }
            if (res) {
                v0 += res[(size_t)r0 * DD + c];
                v1 += res[(size_t)r0 * DD + c + 1];
                v2 += res[(size_t)(r0 + 8) * DD + c];
                v3 += res[(size_t)(r0 + 8) * DD + c + 1];
            }
            if (Cb) {
                *(uint32_t*)(Cb + (size_t)r0 * DD + c) = pack2(v0, v1);
                *(uint32_t*)(Cb + (size_t)(r0 + 8) * DD + c) = pack2(v2, v3);
            } else {
                Cf[(size_t)r0 * DD + c] = v0;
                Cf[(size_t)r0 * DD + c + 1] = v1;
                Cf[(size_t)(r0 + 8) * DD + c] = v2;
                Cf[(size_t)(r0 + 8) * DD + c + 1] = v3;
            }
        }
    }
}

// All 6 input projections. Rows 0..4095 = x, 4096..8191 = y.
// z=2 (V) writes directly into transposed layout vT[b][h][dh][s].
__global__ __launch_bounds__(256, 2) void proj_kernel(
    const bf16* __restrict__ xb, const bf16* __restrict__ yb,
    const bf16* __restrict__ WqT, const bf16* __restrict__ WkT,
    const bf16* __restrict__ WvT,
    bf16* __restrict__ qx, bf16* __restrict__ kx,
    bf16* __restrict__ qy, bf16* __restrict__ ky,
    bf16* __restrict__ vxT, bf16* __restrict__ vyT)
{
    extern __shared__ char sm[];
    const int z = blockIdx.z;
    const int row0g = blockIdx.y * 128;
    const bool isx = (row0g < MM);
    const int row0 = isx ? row0g : row0g - MM;
    const bf16* A = isx ? xb : yb;
    const bf16* W = (z == 0) ? WqT : (z == 1) ? WkT : WvT;
    if (z == 2) {
        gemm_core(A, W, nullptr, nullptr, nullptr, nullptr,
                  isx ? vxT : vyT, row0, blockIdx.x * 128, sm);
    } else {
        bf16* C = (z == 0) ? (isx ? qy : qx) : (isx ? kx : ky);  // q cross-wired
        gemm_core(A, W, nullptr, nullptr, nullptr, C, nullptr,
                  row0, blockIdx.x * 128, sm);
    }
}

__global__ __launch_bounds__(256, 2) void out_kernel(
    const bf16* __restrict__ a1, const bf16* __restrict__ a2,
    const bf16* __restrict__ WoxT, const bf16* __restrict__ WoyT,
    const float* __restrict__ box, const float* __restrict__ boy,
    const float* __restrict__ x, const float* __restrict__ y,
    float* __restrict__ out)
{
    extern __shared__ char sm[];
    const int z = blockIdx.z;
    gemm_core(z ? a2 : a1, z ? WoyT : WoxT, z ? boy : box, z ? y : x,
              out + (size_t)z * MSZ, nullptr, nullptr,
              blockIdx.y * 128, blockIdx.x * 128, sm);
}

// ---------------------------------------------------------------------------
// Fused dual-stream flash attention: 256 q-rows per CTA, 512 thr / 16 warps
// (warp = 16 rows, full 64-key score width, both PV streams). JT=64 keys/iter
// halves cp.async issue work per output row vs 128-row CTAs. Dedicated P,
// warp-private P rows, ONE barrier per iteration. Static softmax.
// Scores computed in two 32-key passes to keep registers under 128.
// ---------------------------------------------------------------------------
#define QST 136                      // Q/K row stride (128 concat + 8)
#define VST 72                       // V and P row stride (64 keys + 8)
#define AJT 64                       // keys per iteration
#define AQE (256*QST)                // 34816 elems
#define AKE (64*QST)                 // 8704 elems (K stage)
#define AVE (64*VST)                 // 4608 elems per V stream
#define ASTG (AKE + 2*AVE)           // 17920 elems per stage
#define APOFF (AQE + 2*ASTG)         // P offset: 70656
#define APE (256*VST)                // 18432 elems
#define ATTN_SMEM_BYTES ((APOFF + APE)*2)   // 178176

__global__ __launch_bounds__(512, 1) void attn_tc(
    const bf16* __restrict__ qx, const bf16* __restrict__ kx, const bf16* __restrict__ vxT,
    const bf16* __restrict__ qy, const bf16* __restrict__ ky, const bf16* __restrict__ vyT,
    bf16* __restrict__ a1o, bf16* __restrict__ a2o)
{
    extern __shared__ char shraw[];
    bf16* Qs = (bf16*)shraw;
    bf16* Ps = Qs + APOFF;           // dedicated P tile [256][VST]

    const int tid = threadIdx.x;
    const int lane = tid & 31;
    const int warp = tid >> 5;       // 0..15
    const int tq = lane >> 2;
    const int tr = lane & 3;
    const int m0 = warp * 16;        // warp's 16 q-rows (0..255)

    // ldmatrix lane constants (byte offsets)
    const int sel = lane >> 3, rin = lane & 7;
    const int aCq = ((m0 + (sel & 1) * 8 + rin) * QST + (sel >> 1) * 8) * 2;  // Q A-frag
    const int aCp = ((m0 + (sel & 1) * 8 + rin) * VST + (sel >> 1) * 8) * 2;  // P A-frag
    const int bCk = (((sel >> 1) * 8 + rin) * QST + (sel & 1) * 8) * 2;       // K B-frag
    const int bCv = (((sel >> 1) * 8 + rin) * VST + (sel & 1) * 8) * 2;       // V B-frag

    const int bh = blockIdx.y;
    const int b = bh >> 4;
    const int h = bh & 15;
    const int q0 = blockIdx.x * 256;
    const size_t base = ((size_t)b * SS) * DD + (size_t)h * DH;
    const size_t vtb = (size_t)bh * DH * SS;

    auto kv_prefetch = [&](int j0, int stg) {
        bf16* Kb = Qs + AQE + stg * ASTG;
        bf16* Vxs = Kb + AKE;
        bf16* Vys = Vxs + AVE;
#pragma unroll
        for (int i = 0; i < 4; i++) {
            const int c = tid + i * 512;   // 0..2047
            if (c < 1024) {
                // K: 64 key-rows x 128 concat dims
                const int row = c >> 4;
                const int half = (c >> 3) & 1;
                const int j = c & 7;
                const bf16* src = (half ? ky : kx) + base + (size_t)(j0 + row) * DD + j * 8;
                CP16(s2u(Kb + row * QST + half * 64 + j * 8), src);
            } else {
                // V: 2 streams x 64 dh-rows x 64 keys
                const int c2 = c - 1024;
                const int t = c2 >> 9;
                const int r = (c2 >> 3) & 63;
                const int j = c2 & 7;
                const bf16* src = (t ? vyT : vxT) + vtb + (size_t)r * SS + j0 + j * 8;
                CP16(s2u((t ? Vys : Vxs) + r * VST + j * 8), src);
            }
        }
        CP_COMMIT();
    };

    // prologue: Q (256 rows x 128 concat) + stage 0
#pragma unroll
    for (int i = 0; i < 8; i++) {
        const int c = tid + i * 512;   // 0..4095
        const int row = c >> 4;
        const int half = (c >> 3) & 1;
        const int j = c & 7;
        const bf16* src = (half ? qy : qx) + base + (size_t)(q0 + row) * DD + j * 8;
        CP16(s2u(Qs + row * QST + half * 64 + j * 8), src);
    }
    CP_COMMIT();
    kv_prefetch(0, 0);

    const uint32_t qsu = s2u(Qs);
    const uint32_t psu = s2u(Ps);

    float lr0 = 0.f, lr1 = 0.f;    // lane-private partial row sums
    float acc1[8][4], acc2[8][4];
#pragma unroll
    for (int nt = 0; nt < 8; nt++)
#pragma unroll
        for (int i = 0; i < 4; i++) { acc1[nt][i] = 0.f; acc2[nt][i] = 0.f; }

    const float SC2 = LOG2E / 16.0f;
    const int pr0 = (m0 + tq) * VST;
    const int pr1 = (m0 + tq + 8) * VST;

    for (int jn = 0; jn < SS / AJT; jn++) {
        CP_WAIT(0);
        __syncthreads();
        if (jn + 1 < SS / AJT) kv_prefetch((jn + 1) * AJT, (jn + 1) & 1);

        bf16* Kb = Qs + AQE + (jn & 1) * ASTG;
        const uint32_t ksu = s2u(Kb);
        const uint32_t vxsu = s2u(Kb + AKE);
        const uint32_t vysu = s2u(Kb + AKE + AVE);

        // ---- scores + softmax in two 32-key passes (register economy) ----
#pragma unroll
        for (int ph = 0; ph < 2; ph++) {
            float s[4][4];
#pragma unroll
            for (int nt = 0; nt < 4; nt++)
#pragma unroll
                for (int i = 0; i < 4; i++) s[nt][i] = 0.f;

#pragma unroll
            for (int k0 = 0; k0 < 128; k0 += 16) {
                const int kb = k0 * 2;
                uint32_t a[4];
                LDSM4(a, qsu + aCq + kb);
#pragma unroll
                for (int np = 0; np < 2; np++) {
                    uint32_t bfr[4];
                    LDSM4(bfr, ksu + bCk + (ph * 2 + np) * (16 * QST * 2) + kb);
                    mma_bf16(s[2 * np],     a, bfr[0], bfr[1]);
                    mma_bf16(s[2 * np + 1], a, bfr[2], bfr[3]);
                }
            }

#pragma unroll
            for (int nt = 0; nt < 4; nt++) {
                const int c = ph * 32 + nt * 8 + 2 * tr;
                const float p0 = exp2f(s[nt][0] * SC2);
                const float p1 = exp2f(s[nt][1] * SC2);
                const float p2 = exp2f(s[nt][2] * SC2);
                const float p3 = exp2f(s[nt][3] * SC2);
                bf162 h01 = __floats2bfloat162_rn(p0, p1);
                bf162 h23 = __floats2bfloat162_rn(p2, p3);
                // sum the bf16-rounded values so l matches what PV consumes
                lr0 += __low2float(h01) + __high2float(h01);
                lr1 += __low2float(h23) + __high2float(h23);
                *(uint32_t*)(Ps + pr0 + c) = *reinterpret_cast<uint32_t*>(&h01);
                *(uint32_t*)(Ps + pr1 + c) = *reinterpret_cast<uint32_t*>(&h23);
            }
        }
        __syncwarp();   // own-warp P visible to own-warp ldmatrix

        // ---- PV: acc1 += P@Vx^T, acc2 += P@Vy^T (k = 64 keys) ----
#pragma unroll
        for (int k0 = 0; k0 < 64; k0 += 16) {
            const int kb = k0 * 2;
            uint32_t a[4];
            LDSM4(a, psu + aCp + kb);
#pragma unroll
            for (int np = 0; np < 4; np++) {
                uint32_t bx[4], by[4];
                LDSM4(bx, vxsu + bCv + np * (16 * VST * 2) + kb);
                mma_bf16(acc1[2 * np],     a, bx[0], bx[1]);
                mma_bf16(acc1[2 * np + 1], a, bx[2], bx[3]);
                LDSM4(by, vysu + bCv + np * (16 * VST * 2) + kb);
                mma_bf16(acc2[2 * np],     a, by[0], by[1]);
                mma_bf16(acc2[2 * np + 1], a, by[2], by[3]);
            }
        }
    }

    // ---- final l reduction across the 4 lanes sharing each row ----
    lr0 += __shfl_xor_sync(0xffffffffu, lr0, 1);
    lr0 += __shfl_xor_sync(0xffffffffu, lr0, 2);
    lr1 += __shfl_xor_sync(0xffffffffu, lr1, 1);
    lr1 += __shfl_xor_sync(0xffffffffu, lr1, 2);

    // ---- normalize + write bf16 ----
    const float inv0 = 1.0f / lr0;
    const float inv1 = 1.0f / lr1;
    const size_t r0g = base + (size_t)(q0 + m0 + tq) * DD;
    const size_t r1g = base + (size_t)(q0 + m0 + tq + 8) * DD;
#pragma unroll
    for (int nt = 0; nt < 8; nt++) {
        const int c = nt * 8 + 2 * tr;
        *(uint32_t*)(a1o + r0g + c) = pack2(acc1[nt][0] * inv0, acc1[nt][1] * inv0);
        *(uint32_t*)(a1o + r1g + c) = pack2(acc1[nt][2] * inv1, acc1[nt][3] * inv1);
        *(uint32_t*)(a2o + r0g + c) = pack2(acc2[nt][0] * inv0, acc2[nt][1] * inv0);
        *(uint32_t*)(a2o + r1g + c) = pack2(acc2[nt][2] * inv1, acc2[nt][3] * inv1);
    }
}

// ---------------------------------------------------------------------------
// Launch
// ---------------------------------------------------------------------------
extern "C" void kernel_launch(void* const* d_in, const int* in_sizes, int n_in,
                              void* d_out, int out_size)
{
    const float* x   = (const float*)d_in[0];
    const float* y   = (const float*)d_in[1];
    const float* Wq  = (const float*)d_in[2];
    const float* Wk  = (const float*)d_in[3];
    const float* Wv  = (const float*)d_in[4];
    const float* Wox = (const float*)d_in[5];
    const float* box = (const float*)d_in[6];
    const float* Woy = (const float*)d_in[7];
    const float* boy = (const float*)d_in[8];
    float* out = (float*)d_out;

    void* p;
    bf16 *xb, *yb, *WqT, *WkT, *WvT, *WoxT, *WoyT;
    bf16 *qx, *kx, *qy, *ky, *vxT, *vyT, *a1, *a2;
    cudaGetSymbolAddress(&p, g_xb);  xb  = (bf16*)p;
    cudaGetSymbolAddress(&p, g_yb);  yb  = (bf16*)p;
    cudaGetSymbolAddress(&p, g_WqT); WqT = (bf16*)p;
    cudaGetSymbolAddress(&p, g_WkT); WkT = (bf16*)p;
    cudaGetSymbolAddress(&p, g_WvT); WvT = (bf16*)p;
    cudaGetSymbolAddress(&p, g_WoxT); WoxT = (bf16*)p;
    cudaGetSymbolAddress(&p, g_WoyT); WoyT = (bf16*)p;
    cudaGetSymbolAddress(&p, g_qx);  qx = (bf16*)p;
    cudaGetSymbolAddress(&p, g_kx);  kx = (bf16*)p;
    cudaGetSymbolAddress(&p, g_qy);  qy = (bf16*)p;
    cudaGetSymbolAddress(&p, g_ky);  ky = (bf16*)p;
    cudaGetSymbolAddress(&p, g_vxT); vxT = (bf16*)p;
    cudaGetSymbolAddress(&p, g_vyT); vyT = (bf16*)p;
    cudaGetSymbolAddress(&p, g_a1);  a1 = (bf16*)p;
    cudaGetSymbolAddress(&p, g_a2);  a2 = (bf16*)p;

    cudaFuncSetAttribute(proj_kernel, cudaFuncAttributeMaxDynamicSharedMemorySize,
                         GEMM_SMEM_BYTES);
    cudaFuncSetAttribute(out_kernel, cudaFuncAttributeMaxDynamicSharedMemorySize,
                         GEMM_SMEM_BYTES);
    cudaFuncSetAttribute(attn_tc, cudaFuncAttributeMaxDynamicSharedMemorySize,
                         ATTN_SMEM_BYTES);

    convxy<<<dim3(MSZ / 1024, 2), 256>>>(x, y, xb, yb);
    wconv<<<dim3(32, 32, 5), 256>>>(Wq, Wk, Wv, Wox, Woy, WqT, WkT, WvT, WoxT, WoyT);

    proj_kernel<<<dim3(DD / 128, 2 * MM / 128, 3), 256, GEMM_SMEM_BYTES>>>(
        xb, yb, WqT, WkT, WvT, qx, kx, qy, ky, vxT, vyT);

    attn_tc<<<dim3(SS / 256, BB * HH), 512, ATTN_SMEM_BYTES>>>(
        qx, kx, vxT, qy, ky, vyT, a1, a2);

    out_kernel<<<dim3(DD / 128, MM / 128, 2), 256, GEMM_SMEM_BYTES>>>(
        a1, a2, WoxT, WoyT, box, boy, x, y, out);
}

// round 14
// speedup vs baseline: 1.1569x; 1.0866x over previous
#include <cuda_runtime.h>
#include <cuda_bf16.h>
#include <math_constants.h>
#include <stdint.h>

#define BB 2
#define SS 2048
#define DD 1024
#define HH 16
#define DH 64
#define MM (BB*SS)
#define MSZ (BB*SS*DD)
#define LOG2E 1.4426950408889634f

typedef __nv_bfloat16 bf16;
typedef __nv_bfloat162 bf162;

// ---------------------------------------------------------------------------
// Device scratch (bf16)
// ---------------------------------------------------------------------------
__device__ bf16 g_xb[MSZ];
__device__ bf16 g_yb[MSZ];
__device__ bf16 g_WqT[DD*DD];
__device__ bf16 g_WkT[DD*DD];
__device__ bf16 g_WvT[DD*DD];
__device__ bf16 g_WoxT[DD*DD];
__device__ bf16 g_WoyT[DD*DD];
__device__ bf16 g_qx[MSZ];
__device__ bf16 g_kx[MSZ];
__device__ bf16 g_qy[MSZ];
__device__ bf16 g_ky[MSZ];
__device__ bf16 g_vxT[MSZ];
__device__ bf16 g_vyT[MSZ];
__device__ bf16 g_a1[MSZ];
__device__ bf16 g_a2[MSZ];

// ---------------------------------------------------------------------------
// Helpers
// ---------------------------------------------------------------------------
__device__ __forceinline__ uint32_t s2u(const void* p) {
    return (uint32_t)__cvta_generic_to_shared(p);
}
#define CP16(dst, src) \
    asm volatile("cp.async.cg.shared.global [%0], [%1], 16;" :: "r"(dst), "l"(src))
#define CP_COMMIT() asm volatile("cp.async.commit_group;")
#define CP_WAIT(N)  asm volatile("cp.async.wait_group %0;" :: "n"(N))

__device__ __forceinline__ void mma_bf16(float c[4], const uint32_t a[4],
                                         uint32_t b0, uint32_t b1) {
    asm volatile(
        "mma.sync.aligned.m16n8k16.row.col.f32.bf16.bf16.f32 "
        "{%0,%1,%2,%3}, {%4,%5,%6,%7}, {%8,%9}, {%0,%1,%2,%3};\n"
        : "+f"(c[0]), "+f"(c[1]), "+f"(c[2]), "+f"(c[3])
        : "r"(a[0]), "r"(a[1]), "r"(a[2]), "r"(a[3]), "r"(b0), "r"(b1));
}

#define LDSM4(r, addr) \
    asm volatile("ldmatrix.sync.aligned.m8n8.x4.shared.b16 {%0,%1,%2,%3}, [%4];" \
                 : "=r"((r)[0]), "=r"((r)[1]), "=r"((r)[2]), "=r"((r)[3]) \
                 : "r"(addr))

__device__ __forceinline__ uint32_t pack2(float lo, float hi) {
    bf162 h = __floats2bfloat162_rn(lo, hi);
    return *reinterpret_cast<uint32_t*>(&h);
}

// ---------------------------------------------------------------------------
// Conversion kernels
// ---------------------------------------------------------------------------
__global__ void convxy(const float* __restrict__ x, const float* __restrict__ y,
                       bf16* __restrict__ xb, bf16* __restrict__ yb)
{
    const size_t i = ((size_t)blockIdx.x * 256 + threadIdx.x) * 4;
    const float* s = blockIdx.y ? y : x;
    bf16* d = blockIdx.y ? yb : xb;
    float4 v = *(const float4*)(s + i);
    uint2 w;
    w.x = pack2(v.x, v.y);
    w.y = pack2(v.z, v.w);
    *(uint2*)(d + i) = w;
}

// transpose + convert: WT[n][k] = bf16(W[k][n])
__global__ void wconv(const float* __restrict__ Wq, const float* __restrict__ Wk,
                      const float* __restrict__ Wv, const float* __restrict__ Wox,
                      const float* __restrict__ Woy,
                      bf16* WqT, bf16* WkT, bf16* WvT, bf16* WoxT, bf16* WoyT)
{
    __shared__ float t[32][33];
    const int z = blockIdx.z;
    const float* W = (z == 0) ? Wq : (z == 1) ? Wk : (z == 2) ? Wv : (z == 3) ? Wox : Woy;
    bf16* WT = (z == 0) ? WqT : (z == 1) ? WkT : (z == 2) ? WvT : (z == 3) ? WoxT : WoyT;
    const int k0 = blockIdx.y * 32, n0 = blockIdx.x * 32;
    const int tid = threadIdx.x;
    const int r = tid >> 3, c4 = (tid & 7) * 4;
    float4 v = *(const float4*)(W + (size_t)(k0 + r) * DD + n0 + c4);
    t[r][c4] = v.x; t[r][c4 + 1] = v.y; t[r][c4 + 2] = v.z; t[r][c4 + 3] = v.w;
    __syncthreads();
    uint2 w;
    w.x = pack2(t[c4][r], t[c4 + 1][r]);
    w.y = pack2(t[c4 + 2][r], t[c4 + 3][r]);
    *(uint2*)(WT + (size_t)(n0 + r) * DD + k0 + c4) = w;
}

// ---------------------------------------------------------------------------
// bf16 GEMM core: C[128,128] tile of A[.,1024](bf16,[m][k]) @ WT(bf16,[n][k])
// 256 thr / 8 warps (4m x 2n, warp tile 32x64). cp.async 4-stage, k-tile 32.
// Fragment loads via ldmatrix.x4. Optional transposed-V output (CT).
// ---------------------------------------------------------------------------
#define KT 32
#define SR 40                      // smem row stride (elements)
#define TSTG (128*SR)              // elements per (A|B) stage
#define GSTG 4
#define GEMM_SMEM_BYTES (GSTG*2*TSTG*2)   // 81920

__device__ __forceinline__ void gemm_core(
    const bf16* __restrict__ A, const bf16* __restrict__ WT,
    const float* __restrict__ bias, const float* __restrict__ res,
    float* __restrict__ Cf, bf16* __restrict__ Cb, bf16* __restrict__ CT,
    int row0, int col0, char* smraw)
{
    bf16* As = (bf16*)smraw;
    bf16* Bs = As + GSTG * TSTG;

    const int tid = threadIdx.x;
    const int lane = tid & 31;
    const int warp = tid >> 5;
    const int m_base = (warp >> 1) * 32;
    const int n_base = (warp & 1) * 64;
    const int tq = lane >> 2;
    const int tr = lane & 3;

    // ldmatrix lane-address constants (byte offsets into stage)
    const int sel = lane >> 3, rin = lane & 7;
    const int aC0 = ((m_base + (sel & 1) * 8 + rin) * SR + (sel >> 1) * 8) * 2;
    const int aC1 = aC0 + 16 * SR * 2;
    const int bC  = ((n_base + (sel >> 1) * 8 + rin) * SR + (sel & 1) * 8) * 2;

    auto prefetch = [&](int kt) {
        const int stg = kt & (GSTG - 1);
        const int k0 = kt * KT;
        bf16* as = As + stg * TSTG;
        bf16* bs = Bs + stg * TSTG;
#pragma unroll
        for (int i = 0; i < 4; i++) {
            const int c = tid + i * 256;           // 0..1023
            const int r = (c >> 2) & 127;
            const int jc = (c & 3) * 8;
            if (c < 512) {
                CP16(s2u(as + r * SR + jc), A + (size_t)(row0 + r) * DD + k0 + jc);
            } else {
                CP16(s2u(bs + r * SR + jc), WT + (size_t)(col0 + r) * DD + k0 + jc);
            }
        }
        CP_COMMIT();
    };

    float acc[2][8][4];
#pragma unroll
    for (int mt = 0; mt < 2; mt++)
#pragma unroll
        for (int nt = 0; nt < 8; nt++)
#pragma unroll
            for (int i = 0; i < 4; i++) acc[mt][nt][i] = 0.f;

    const int NK = DD / KT;  // 32
    prefetch(0); prefetch(1); prefetch(2);

    for (int kt = 0; kt < NK; kt++) {
        if (kt < NK - 2) { CP_WAIT(2); } else { CP_WAIT(0); }
        __syncthreads();
        if (kt + 3 < NK) prefetch(kt + 3);

        const int stg = kt & (GSTG - 1);
        const uint32_t asu = s2u(As + stg * TSTG);
        const uint32_t bsu = s2u(Bs + stg * TSTG);
#pragma unroll
        for (int ks = 0; ks < 2; ks++) {
            const int kb = ks * 32;   // byte offset of 16-elem k block
            uint32_t a0[4], a1[4];
            LDSM4(a0, asu + aC0 + kb);
            LDSM4(a1, asu + aC1 + kb);
#pragma unroll
            for (int np = 0; np < 4; np++) {
                uint32_t bfr[4];
                LDSM4(bfr, bsu + bC + np * (16 * SR * 2) + kb);
                mma_bf16(acc[0][2 * np],     a0, bfr[0], bfr[1]);
                mma_bf16(acc[0][2 * np + 1], a0, bfr[2], bfr[3]);
                mma_bf16(acc[1][2 * np],     a1, bfr[0], bfr[1]);
                mma_bf16(acc[1][2 * np + 1], a1, bfr[2], bfr[3]);
            }
        }
    }

    if (CT) {
        // ---- transposed-V epilogue: stage in smem, write vT[bh][dh][s] ----
        __syncthreads();                        // all warps done with stage smem
        bf16* Se = (bf16*)smraw;                // [128][136]
#pragma unroll
        for (int mt = 0; mt < 2; mt++) {
            const int m = m_base + mt * 16 + tq;
#pragma unroll
            for (int nt = 0; nt < 8; nt++) {
                const int c = n_base + nt * 8 + 2 * tr;
                *(uint32_t*)(Se + m * 136 + c) = pack2(acc[mt][nt][0], acc[mt][nt][1]);
                *(uint32_t*)(Se + (m + 8) * 136 + c) = pack2(acc[mt][nt][2], acc[mt][nt][3]);
            }
        }
        __syncthreads();
        const int bb = row0 >> 11;
        const int s_base = row0 & 2047;
#pragma unroll
        for (int ii = 0; ii < 8; ii++) {
            const int i = tid + ii * 256;       // 0..2047
            const int dh_l = i & 127;
            const int sc = (i >> 7) * 8;
            bf162 p0, p1, p2, p3;
            p0.x = Se[(sc + 0) * 136 + dh_l]; p0.y = Se[(sc + 1) * 136 + dh_l];
            p1.x = Se[(sc + 2) * 136 + dh_l]; p1.y = Se[(sc + 3) * 136 + dh_l];
            p2.x = Se[(sc + 4) * 136 + dh_l]; p2.y = Se[(sc + 5) * 136 + dh_l];
            p3.x = Se[(sc + 6) * 136 + dh_l]; p3.y = Se[(sc + 7) * 136 + dh_l];
            uint4 w;
            w.x = *reinterpret_cast<uint32_t*>(&p0);
            w.y = *reinterpret_cast<uint32_t*>(&p1);
            w.z = *reinterpret_cast<uint32_t*>(&p2);
            w.w = *reinterpret_cast<uint32_t*>(&p3);
            const int cg = col0 + dh_l;
            const int hh = cg >> 6, dh = cg & 63;
            *(uint4*)(CT + ((size_t)((bb * 16 + hh) * 64 + dh)) * SS + s_base + sc) = w;
        }
        return;
    }

    // ---- standard epilogue ----
#pragma unroll
    for (int mt = 0; mt < 2; mt++) {
        const int r0 = row0 + m_base + mt * 16 + tq;
#pragma unroll
        for (int nt = 0; nt < 8; nt++) {
            const int c = col0 + n_base + nt * 8 + 2 * tr;
            float v0 = acc[mt][nt][0], v1 = acc[mt][nt][1];
            float v2 = acc[mt][nt][2], v3 = acc[mt][nt][3];
            if (bias) {
                v0 += bias[c]; v1 += bias[c + 1];
                v2 += bias[c]; v3 += bias[c + 1];
            }
            if (res) {
                v0 += res[(size_t)r0 * DD + c];
                v1 += res[(size_t)r0 * DD + c + 1];
                v2 += res[(size_t)(r0 + 8) * DD + c];
                v3 += res[(size_t)(r0 + 8) * DD + c + 1];
            }
            if (Cb) {
                *(uint32_t*)(Cb + (size_t)r0 * DD + c) = pack2(v0, v1);
                *(uint32_t*)(Cb + (size_t)(r0 + 8) * DD + c) = pack2(v2, v3);
            } else {
                Cf[(size_t)r0 * DD + c] = v0;
                Cf[(size_t)r0 * DD + c + 1] = v1;
                Cf[(size_t)(r0 + 8) * DD + c] = v2;
                Cf[(size_t)(r0 + 8) * DD + c + 1] = v3;
            }
        }
    }
}

// All 6 input projections. Rows 0..4095 = x, 4096..8191 = y.
// z=2 (V) writes directly into transposed layout vT[b][h][dh][s].
__global__ __launch_bounds__(256, 2) void proj_kernel(
    const bf16* __restrict__ xb, const bf16* __restrict__ yb,
    const bf16* __restrict__ WqT, const bf16* __restrict__ WkT,
    const bf16* __restrict__ WvT,
    bf16* __restrict__ qx, bf16* __restrict__ kx,
    bf16* __restrict__ qy, bf16* __restrict__ ky,
    bf16* __restrict__ vxT, bf16* __restrict__ vyT)
{
    extern __shared__ char sm[];
    const int z = blockIdx.z;
    const int row0g = blockIdx.y * 128;
    const bool isx = (row0g < MM);
    const int row0 = isx ? row0g : row0g - MM;
    const bf16* A = isx ? xb : yb;
    const bf16* W = (z == 0) ? WqT : (z == 1) ? WkT : WvT;
    if (z == 2) {
        gemm_core(A, W, nullptr, nullptr, nullptr, nullptr,
                  isx ? vxT : vyT, row0, blockIdx.x * 128, sm);
    } else {
        bf16* C = (z == 0) ? (isx ? qy : qx) : (isx ? kx : ky);  // q cross-wired
        gemm_core(A, W, nullptr, nullptr, nullptr, C, nullptr,
                  row0, blockIdx.x * 128, sm);
    }
}

__global__ __launch_bounds__(256, 2) void out_kernel(
    const bf16* __restrict__ a1, const bf16* __restrict__ a2,
    const bf16* __restrict__ WoxT, const bf16* __restrict__ WoyT,
    const float* __restrict__ box, const float* __restrict__ boy,
    const float* __restrict__ x, const float* __restrict__ y,
    float* __restrict__ out)
{
    extern __shared__ char sm[];
    const int z = blockIdx.z;
    gemm_core(z ? a2 : a1, z ? WoyT : WoxT, z ? boy : box, z ? y : x,
              out + (size_t)z * MSZ, nullptr, nullptr,
              blockIdx.y * 128, blockIdx.x * 128, sm);
}

// ---------------------------------------------------------------------------
// Fused dual-stream flash attention: 256 q-rows / CTA, 256 thr / 8 warps,
// warp tile m=32 (halves K/V smem reads vs 16 warps). JT=64 keys/iter.
// REGISTER-RESIDENT P: score C-fragments are exp'd and packed directly into
// PV A-fragments (no P smem buffer, no extra syncs). Static softmax.
// ---------------------------------------------------------------------------
#define QST 136                      // Q/K row stride (128 concat + 8)
#define VST 72                       // V row stride (64 keys + 8)
#define AJT 64                       // keys per iteration
#define AQE (256*QST)                // 34816 elems
#define AKE (64*QST)                 // 8704 elems (K stage)
#define AVE (64*VST)                 // 4608 elems per V stream
#define ASTG (AKE + 2*AVE)           // 17920 elems per stage
#define ATTN_SMEM_BYTES ((AQE + 2*ASTG)*2)   // 141312

__global__ __launch_bounds__(256, 1) void attn_tc(
    const bf16* __restrict__ qx, const bf16* __restrict__ kx, const bf16* __restrict__ vxT,
    const bf16* __restrict__ qy, const bf16* __restrict__ ky, const bf16* __restrict__ vyT,
    bf16* __restrict__ a1o, bf16* __restrict__ a2o)
{
    extern __shared__ char shraw[];
    bf16* Qs = (bf16*)shraw;

    const int tid = threadIdx.x;
    const int lane = tid & 31;
    const int warp = tid >> 5;       // 0..7
    const int tq = lane >> 2;
    const int tr = lane & 3;
    const int m0 = warp * 32;        // warp's 32 q-rows

    // ldmatrix lane constants (byte offsets)
    const int sel = lane >> 3, rin = lane & 7;
    const int aCq  = ((m0 + (sel & 1) * 8 + rin) * QST + (sel >> 1) * 8) * 2;  // Q m-tile 0
    const int aCq2 = aCq + 16 * QST * 2;                                       // Q m-tile 1
    const int bCk = (((sel >> 1) * 8 + rin) * QST + (sel & 1) * 8) * 2;        // K B-frag
    const int bCv = (((sel >> 1) * 8 + rin) * VST + (sel & 1) * 8) * 2;        // V B-frag

    const int bh = blockIdx.y;
    const int b = bh >> 4;
    const int h = bh & 15;
    const int q0 = blockIdx.x * 256;
    const size_t base = ((size_t)b * SS) * DD + (size_t)h * DH;
    const size_t vtb = (size_t)bh * DH * SS;

    auto kv_prefetch = [&](int j0, int stg) {
        bf16* Kb = Qs + AQE + stg * ASTG;
        bf16* Vxs = Kb + AKE;
        bf16* Vys = Vxs + AVE;
#pragma unroll
        for (int i = 0; i < 8; i++) {
            const int c = tid + i * 256;   // 0..2047
            if (c < 1024) {
                // K: 64 key-rows x 128 concat dims
                const int row = c >> 4;
                const int half = (c >> 3) & 1;
                const int j = c & 7;
                const bf16* src = (half ? ky : kx) + base + (size_t)(j0 + row) * DD + j * 8;
                CP16(s2u(Kb + row * QST + half * 64 + j * 8), src);
            } else {
                // V: 2 streams x 64 dh-rows x 64 keys
                const int c2 = c - 1024;
                const int t = c2 >> 9;
                const int r = (c2 >> 3) & 63;
                const int j = c2 & 7;
                const bf16* src = (t ? vyT : vxT) + vtb + (size_t)r * SS + j0 + j * 8;
                CP16(s2u((t ? Vys : Vxs) + r * VST + j * 8), src);
            }
        }
        CP_COMMIT();
    };

    // prologue: Q (256 rows x 128 concat) + stage 0
#pragma unroll
    for (int i = 0; i < 16; i++) {
        const int c = tid + i * 256;   // 0..4095
        const int row = c >> 4;
        const int half = (c >> 3) & 1;
        const int j = c & 7;
        const bf16* src = (half ? qy : qx) + base + (size_t)(q0 + row) * DD + j * 8;
        CP16(s2u(Qs + row * QST + half * 64 + j * 8), src);
    }
    CP_COMMIT();
    kv_prefetch(0, 0);

    const uint32_t qsu = s2u(Qs);

    float lr[2][2] = {{0.f, 0.f}, {0.f, 0.f}};   // [m-tile][row-half] partial sums
    float acc1[2][8][4], acc2[2][8][4];
#pragma unroll
    for (int mf = 0; mf < 2; mf++)
#pragma unroll
        for (int nt = 0; nt < 8; nt++)
#pragma unroll
            for (int i = 0; i < 4; i++) { acc1[mf][nt][i] = 0.f; acc2[mf][nt][i] = 0.f; }

    const float SC2 = LOG2E / 16.0f;

    for (int jn = 0; jn < SS / AJT; jn++) {
        CP_WAIT(0);
        __syncthreads();
        if (jn + 1 < SS / AJT) kv_prefetch((jn + 1) * AJT, (jn + 1) & 1);

        bf16* Kb = Qs + AQE + (jn & 1) * ASTG;
        const uint32_t ksu = s2u(Kb);
        const uint32_t vxsu = s2u(Kb + AKE);
        const uint32_t vysu = s2u(Kb + AKE + AVE);

        // ---- scores: S[32 x 64] over concat k=128 ----
        float s[2][8][4];
#pragma unroll
        for (int mf = 0; mf < 2; mf++)
#pragma unroll
            for (int nt = 0; nt < 8; nt++)
#pragma unroll
                for (int i = 0; i < 4; i++) s[mf][nt][i] = 0.f;

#pragma unroll
        for (int k0 = 0; k0 < 128; k0 += 16) {
            const int kb = k0 * 2;
            uint32_t a0[4], a1[4];
            LDSM4(a0, qsu + aCq + kb);
            LDSM4(a1, qsu + aCq2 + kb);
#pragma unroll
            for (int np = 0; np < 4; np++) {
                uint32_t bfr[4];
                LDSM4(bfr, ksu + bCk + np * (16 * QST * 2) + kb);
                mma_bf16(s[0][2 * np],     a0, bfr[0], bfr[1]);
                mma_bf16(s[0][2 * np + 1], a0, bfr[2], bfr[3]);
                mma_bf16(s[1][2 * np],     a1, bfr[0], bfr[1]);
                mma_bf16(s[1][2 * np + 1], a1, bfr[2], bfr[3]);
            }
        }

        // ---- static softmax + pack P into PV A-fragments (registers) ----
        // C-frag (c0,c1 row tq; c2,c3 row tq+8) -> A-frag of PV mma:
        // a0=pack2(even-tile c0,c1), a1=pack2(even c2,c3),
        // a2=pack2(odd c0,c1),       a3=pack2(odd c2,c3)
        uint32_t pp[2][4][4];
#pragma unroll
        for (int mf = 0; mf < 2; mf++)
#pragma unroll
            for (int nt = 0; nt < 8; nt++) {
                const float p0 = exp2f(s[mf][nt][0] * SC2);
                const float p1 = exp2f(s[mf][nt][1] * SC2);
                const float p2 = exp2f(s[mf][nt][2] * SC2);
                const float p3 = exp2f(s[mf][nt][3] * SC2);
                bf162 h01 = __floats2bfloat162_rn(p0, p1);
                bf162 h23 = __floats2bfloat162_rn(p2, p3);
                // sum the bf16-rounded values so l matches what PV consumes
                lr[mf][0] += __low2float(h01) + __high2float(h01);
                lr[mf][1] += __low2float(h23) + __high2float(h23);
                pp[mf][nt >> 1][(nt & 1) * 2 + 0] = *reinterpret_cast<uint32_t*>(&h01);
                pp[mf][nt >> 1][(nt & 1) * 2 + 1] = *reinterpret_cast<uint32_t*>(&h23);
            }

        // ---- PV: acc1 += P@Vx^T, acc2 += P@Vy^T (k = 64 keys, 4 blocks) ----
#pragma unroll
        for (int kb4 = 0; kb4 < 4; kb4++) {
            const int kb = kb4 * 32;   // 16 keys = 32 bytes
#pragma unroll
            for (int np = 0; np < 4; np++) {
                uint32_t bx[4], by[4];
                LDSM4(bx, vxsu + bCv + np * (16 * VST * 2) + kb);
                mma_bf16(acc1[0][2 * np],     pp[0][kb4], bx[0], bx[1]);
                mma_bf16(acc1[0][2 * np + 1], pp[0][kb4], bx[2], bx[3]);
                mma_bf16(acc1[1][2 * np],     pp[1][kb4], bx[0], bx[1]);
                mma_bf16(acc1[1][2 * np + 1], pp[1][kb4], bx[2], bx[3]);
                LDSM4(by, vysu + bCv + np * (16 * VST * 2) + kb);
                mma_bf16(acc2[0][2 * np],     pp[0][kb4], by[0], by[1]);
                mma_bf16(acc2[0][2 * np + 1], pp[0][kb4], by[2], by[3]);
                mma_bf16(acc2[1][2 * np],     pp[1][kb4], by[0], by[1]);
                mma_bf16(acc2[1][2 * np + 1], pp[1][kb4], by[2], by[3]);
            }
        }
    }

    // ---- final l reduction across the 4 lanes sharing each row ----
#pragma unroll
    for (int mf = 0; mf < 2; mf++) {
#pragma unroll
        for (int r = 0; r < 2; r++) {
            lr[mf][r] += __shfl_xor_sync(0xffffffffu, lr[mf][r], 1);
            lr[mf][r] += __shfl_xor_sync(0xffffffffu, lr[mf][r], 2);
        }
    }

    // ---- normalize + write bf16 ----
#pragma unroll
    for (int mf = 0; mf < 2; mf++) {
        const float inv0 = 1.0f / lr[mf][0];
        const float inv1 = 1.0f / lr[mf][1];
        const size_t r0g = base + (size_t)(q0 + m0 + mf * 16 + tq) * DD;
        const size_t r1g = base + (size_t)(q0 + m0 + mf * 16 + tq + 8) * DD;
#pragma unroll
        for (int nt = 0; nt < 8; nt++) {
            const int c = nt * 8 + 2 * tr;
            *(uint32_t*)(a1o + r0g + c) = pack2(acc1[mf][nt][0] * inv0, acc1[mf][nt][1] * inv0);
            *(uint32_t*)(a1o + r1g + c) = pack2(acc1[mf][nt][2] * inv1, acc1[mf][nt][3] * inv1);
            *(uint32_t*)(a2o + r0g + c) = pack2(acc2[mf][nt][0] * inv0, acc2[mf][nt][1] * inv0);
            *(uint32_t*)(a2o + r1g + c) = pack2(acc2[mf][nt][2] * inv1, acc2[mf][nt][3] * inv1);
        }
    }
}

// ---------------------------------------------------------------------------
// Launch
// ---------------------------------------------------------------------------
extern "C" void kernel_launch(void* const* d_in, const int* in_sizes, int n_in,
                              void* d_out, int out_size)
{
    const float* x   = (const float*)d_in[0];
    const float* y   = (const float*)d_in[1];
    const float* Wq  = (const float*)d_in[2];
    const float* Wk  = (const float*)d_in[3];
    const float* Wv  = (const float*)d_in[4];
    const float* Wox = (const float*)d_in[5];
    const float* box = (const float*)d_in[6];
    const float* Woy = (const float*)d_in[7];
    const float* boy = (const float*)d_in[8];
    float* out = (float*)d_out;

    void* p;
    bf16 *xb, *yb, *WqT, *WkT, *WvT, *WoxT, *WoyT;
    bf16 *qx, *kx, *qy, *ky, *vxT, *vyT, *a1, *a2;
    cudaGetSymbolAddress(&p, g_xb);  xb  = (bf16*)p;
    cudaGetSymbolAddress(&p, g_yb);  yb  = (bf16*)p;
    cudaGetSymbolAddress(&p, g_WqT); WqT = (bf16*)p;
    cudaGetSymbolAddress(&p, g_WkT); WkT = (bf16*)p;
    cudaGetSymbolAddress(&p, g_WvT); WvT = (bf16*)p;
    cudaGetSymbolAddress(&p, g_WoxT); WoxT = (bf16*)p;
    cudaGetSymbolAddress(&p, g_WoyT); WoyT = (bf16*)p;
    cudaGetSymbolAddress(&p, g_qx);  qx = (bf16*)p;
    cudaGetSymbolAddress(&p, g_kx);  kx = (bf16*)p;
    cudaGetSymbolAddress(&p, g_qy);  qy = (bf16*)p;
    cudaGetSymbolAddress(&p, g_ky);  ky = (bf16*)p;
    cudaGetSymbolAddress(&p, g_vxT); vxT = (bf16*)p;
    cudaGetSymbolAddress(&p, g_vyT); vyT = (bf16*)p;
    cudaGetSymbolAddress(&p, g_a1);  a1 = (bf16*)p;
    cudaGetSymbolAddress(&p, g_a2);  a2 = (bf16*)p;

    cudaFuncSetAttribute(proj_kernel, cudaFuncAttributeMaxDynamicSharedMemorySize,
                         GEMM_SMEM_BYTES);
    cudaFuncSetAttribute(out_kernel, cudaFuncAttributeMaxDynamicSharedMemorySize,
                         GEMM_SMEM_BYTES);
    cudaFuncSetAttribute(attn_tc, cudaFuncAttributeMaxDynamicSharedMemorySize,
                         ATTN_SMEM_BYTES);

    convxy<<<dim3(MSZ / 1024, 2), 256>>>(x, y, xb, yb);
    wconv<<<dim3(32, 32, 5), 256>>>(Wq, Wk, Wv, Wox, Woy, WqT, WkT, WvT, WoxT, WoyT);

    proj_kernel<<<dim3(DD / 128, 2 * MM / 128, 3), 256, GEMM_SMEM_BYTES>>>(
        xb, yb, WqT, WkT, WvT, qx, kx, qy, ky, vxT, vyT);

    attn_tc<<<dim3(SS / 256, BB * HH), 256, ATTN_SMEM_BYTES>>>(
        qx, kx, vxT, qy, ky, vyT, a1, a2);

    out_kernel<<<dim3(DD / 128, MM / 128, 2), 256, GEMM_SMEM_BYTES>>>(
        a1, a2, WoxT, WoyT, box, boy, x, y, out);
}

// round 16
// speedup vs baseline: 1.1915x; 1.0299x over previous
#include <cuda_runtime.h>
#include <cuda_bf16.h>
#include <math_constants.h>
#include <stdint.h>

#define BB 2
#define SS 2048
#define DD 1024
#define HH 16
#define DH 64
#define MM (BB*SS)
#define MSZ (BB*SS*DD)
#define LOG2E 1.4426950408889634f
#define QSCALE (LOG2E / 16.0f)

typedef __nv_bfloat16 bf16;
typedef __nv_bfloat162 bf162;

// ---------------------------------------------------------------------------
// Device scratch (bf16)
// ---------------------------------------------------------------------------
__device__ bf16 g_xb[MSZ];
__device__ bf16 g_yb[MSZ];
__device__ bf16 g_WqT[DD*DD];
__device__ bf16 g_WkT[DD*DD];
__device__ bf16 g_WvT[DD*DD];
__device__ bf16 g_WoxT[DD*DD];
__device__ bf16 g_WoyT[DD*DD];
__device__ bf16 g_qx[MSZ];
__device__ bf16 g_kx[MSZ];
__device__ bf16 g_qy[MSZ];
__device__ bf16 g_ky[MSZ];
__device__ bf16 g_vxT[MSZ];
__device__ bf16 g_vyT[MSZ];
__device__ bf16 g_a1[MSZ];
__device__ bf16 g_a2[MSZ];

// ---------------------------------------------------------------------------
// Helpers
// ---------------------------------------------------------------------------
__device__ __forceinline__ uint32_t s2u(const void* p) {
    return (uint32_t)__cvta_generic_to_shared(p);
}
#define CP16(dst, src) \
    asm volatile("cp.async.cg.shared.global [%0], [%1], 16;" :: "r"(dst), "l"(src))
#define CP_COMMIT() asm volatile("cp.async.commit_group;")
#define CP_WAIT(N)  asm volatile("cp.async.wait_group %0;" :: "n"(N))

__device__ __forceinline__ void mma_bf16(float c[4], const uint32_t a[4],
                                         uint32_t b0, uint32_t b1) {
    asm volatile(
        "mma.sync.aligned.m16n8k16.row.col.f32.bf16.bf16.f32 "
        "{%0,%1,%2,%3}, {%4,%5,%6,%7}, {%8,%9}, {%0,%1,%2,%3};\n"
        : "+f"(c[0]), "+f"(c[1]), "+f"(c[2]), "+f"(c[3])
        : "r"(a[0]), "r"(a[1]), "r"(a[2]), "r"(a[3]), "r"(b0), "r"(b1));
}

#define LDSM4(r, addr) \
    asm volatile("ldmatrix.sync.aligned.m8n8.x4.shared.b16 {%0,%1,%2,%3}, [%4];" \
                 : "=r"((r)[0]), "=r"((r)[1]), "=r"((r)[2]), "=r"((r)[3]) \
                 : "r"(addr))

__device__ __forceinline__ uint32_t pack2(float lo, float hi) {
    bf162 h = __floats2bfloat162_rn(lo, hi);
    return *reinterpret_cast<uint32_t*>(&h);
}

// ---------------------------------------------------------------------------
// Conversion kernels
// ---------------------------------------------------------------------------
__global__ void convxy(const float* __restrict__ x, const float* __restrict__ y,
                       bf16* __restrict__ xb, bf16* __restrict__ yb)
{
    const size_t i = ((size_t)blockIdx.x * 256 + threadIdx.x) * 4;
    const float* s = blockIdx.y ? y : x;
    bf16* d = blockIdx.y ? yb : xb;
    float4 v = *(const float4*)(s + i);
    uint2 w;
    w.x = pack2(v.x, v.y);
    w.y = pack2(v.z, v.w);
    *(uint2*)(d + i) = w;
}

// transpose + convert: WT[n][k] = bf16(W[k][n])
__global__ void wconv(const float* __restrict__ Wq, const float* __restrict__ Wk,
                      const float* __restrict__ Wv, const float* __restrict__ Wox,
                      const float* __restrict__ Woy,
                      bf16* WqT, bf16* WkT, bf16* WvT, bf16* WoxT, bf16* WoyT)
{
    __shared__ float t[32][33];
    const int z = blockIdx.z;
    const float* W = (z == 0) ? Wq : (z == 1) ? Wk : (z == 2) ? Wv : (z == 3) ? Wox : Woy;
    bf16* WT = (z == 0) ? WqT : (z == 1) ? WkT : (z == 2) ? WvT : (z == 3) ? WoxT : WoyT;
    const int k0 = blockIdx.y * 32, n0 = blockIdx.x * 32;
    const int tid = threadIdx.x;
    const int r = tid >> 3, c4 = (tid & 7) * 4;
    float4 v = *(const float4*)(W + (size_t)(k0 + r) * DD + n0 + c4);
    t[r][c4] = v.x; t[r][c4 + 1] = v.y; t[r][c4 + 2] = v.z; t[r][c4 + 3] = v.w;
    __syncthreads();
    uint2 w;
    w.x = pack2(t[c4][r], t[c4 + 1][r]);
    w.y = pack2(t[c4 + 2][r], t[c4 + 3][r]);
    *(uint2*)(WT + (size_t)(n0 + r) * DD + k0 + c4) = w;
}

// ---------------------------------------------------------------------------
// bf16 GEMM core: C[128,128] tile of A[.,1024](bf16,[m][k]) @ WT(bf16,[n][k])
// 256 thr / 8 warps (4m x 2n, warp tile 32x64). cp.async 4-stage, k-tile 32.
// Fragment loads via ldmatrix.x4. Optional transposed-V output (CT).
// oscale multiplies the output (used to fold the softmax scale into Q).
// ---------------------------------------------------------------------------
#define KT 32
#define SR 40                      // smem row stride (elements)
#define TSTG (128*SR)              // elements per (A|B) stage
#define GSTG 4
#define GEMM_SMEM_BYTES (GSTG*2*TSTG*2)   // 81920

__device__ __forceinline__ void gemm_core(
    const bf16* __restrict__ A, const bf16* __restrict__ WT,
    const float* __restrict__ bias, const float* __restrict__ res,
    float* __restrict__ Cf, bf16* __restrict__ Cb, bf16* __restrict__ CT,
    int row0, int col0, char* smraw, float oscale)
{
    bf16* As = (bf16*)smraw;
    bf16* Bs = As + GSTG * TSTG;

    const int tid = threadIdx.x;
    const int lane = tid & 31;
    const int warp = tid >> 5;
    const int m_base = (warp >> 1) * 32;
    const int n_base = (warp & 1) * 64;
    const int tq = lane >> 2;
    const int tr = lane & 3;

    // ldmatrix lane-address constants (byte offsets into stage)
    const int sel = lane >> 3, rin = lane & 7;
    const int aC0 = ((m_base + (sel & 1) * 8 + rin) * SR + (sel >> 1) * 8) * 2;
    const int aC1 = aC0 + 16 * SR * 2;
    const int bC  = ((n_base + (sel >> 1) * 8 + rin) * SR + (sel & 1) * 8) * 2;

    auto prefetch = [&](int kt) {
        const int stg = kt & (GSTG - 1);
        const int k0 = kt * KT;
        bf16* as = As + stg * TSTG;
        bf16* bs = Bs + stg * TSTG;
#pragma unroll
        for (int i = 0; i < 4; i++) {
            const int c = tid + i * 256;           // 0..1023
            const int r = (c >> 2) & 127;
            const int jc = (c & 3) * 8;
            if (c < 512) {
                CP16(s2u(as + r * SR + jc), A + (size_t)(row0 + r) * DD + k0 + jc);
            } else {
                CP16(s2u(bs + r * SR + jc), WT + (size_t)(col0 + r) * DD + k0 + jc);
            }
        }
        CP_COMMIT();
    };

    float acc[2][8][4];
#pragma unroll
    for (int mt = 0; mt < 2; mt++)
#pragma unroll
        for (int nt = 0; nt < 8; nt++)
#pragma unroll
            for (int i = 0; i < 4; i++) acc[mt][nt][i] = 0.f;

    const int NK = DD / KT;  // 32
    prefetch(0); prefetch(1); prefetch(2);

    for (int kt = 0; kt < NK; kt++) {
        if (kt < NK - 2) { CP_WAIT(2); } else { CP_WAIT(0); }
        __syncthreads();
        if (kt + 3 < NK) prefetch(kt + 3);

        const int stg = kt & (GSTG - 1);
        const uint32_t asu = s2u(As + stg * TSTG);
        const uint32_t bsu = s2u(Bs + stg * TSTG);
#pragma unroll
        for (int ks = 0; ks < 2; ks++) {
            const int kb = ks * 32;   // byte offset of 16-elem k block
            uint32_t a0[4], a1[4];
            LDSM4(a0, asu + aC0 + kb);
            LDSM4(a1, asu + aC1 + kb);
#pragma unroll
            for (int np = 0; np < 4; np++) {
                uint32_t bfr[4];
                LDSM4(bfr, bsu + bC + np * (16 * SR * 2) + kb);
                mma_bf16(acc[0][2 * np],     a0, bfr[0], bfr[1]);
                mma_bf16(acc[0][2 * np + 1], a0, bfr[2], bfr[3]);
                mma_bf16(acc[1][2 * np],     a1, bfr[0], bfr[1]);
                mma_bf16(acc[1][2 * np + 1], a1, bfr[2], bfr[3]);
            }
        }
    }

    if (CT) {
        // ---- transposed-V epilogue: stage in smem, write vT[bh][dh][s] ----
        __syncthreads();                        // all warps done with stage smem
        bf16* Se = (bf16*)smraw;                // [128][136]
#pragma unroll
        for (int mt = 0; mt < 2; mt++) {
            const int m = m_base + mt * 16 + tq;
#pragma unroll
            for (int nt = 0; nt < 8; nt++) {
                const int c = n_base + nt * 8 + 2 * tr;
                *(uint32_t*)(Se + m * 136 + c) = pack2(acc[mt][nt][0], acc[mt][nt][1]);
                *(uint32_t*)(Se + (m + 8) * 136 + c) = pack2(acc[mt][nt][2], acc[mt][nt][3]);
            }
        }
        __syncthreads();
        const int bb = row0 >> 11;
        const int s_base = row0 & 2047;
#pragma unroll
        for (int ii = 0; ii < 8; ii++) {
            const int i = tid + ii * 256;       // 0..2047
            const int dh_l = i & 127;
            const int sc = (i >> 7) * 8;
            bf162 p0, p1, p2, p3;
            p0.x = Se[(sc + 0) * 136 + dh_l]; p0.y = Se[(sc + 1) * 136 + dh_l];
            p1.x = Se[(sc + 2) * 136 + dh_l]; p1.y = Se[(sc + 3) * 136 + dh_l];
            p2.x = Se[(sc + 4) * 136 + dh_l]; p2.y = Se[(sc + 5) * 136 + dh_l];
            p3.x = Se[(sc + 6) * 136 + dh_l]; p3.y = Se[(sc + 7) * 136 + dh_l];
            uint4 w;
            w.x = *reinterpret_cast<uint32_t*>(&p0);
            w.y = *reinterpret_cast<uint32_t*>(&p1);
            w.z = *reinterpret_cast<uint32_t*>(&p2);
            w.w = *reinterpret_cast<uint32_t*>(&p3);
            const int cg = col0 + dh_l;
            const int hh = cg >> 6, dh = cg & 63;
            *(uint4*)(CT + ((size_t)((bb * 16 + hh) * 64 + dh)) * SS + s_base + sc) = w;
        }
        return;
    }

    // ---- standard epilogue ----
#pragma unroll
    for (int mt = 0; mt < 2; mt++) {
        const int r0 = row0 + m_base + mt * 16 + tq;
#pragma unroll
        for (int nt = 0; nt < 8; nt++) {
            const int c = col0 + n_base + nt * 8 + 2 * tr;
            float v0 = acc[mt][nt][0] * oscale, v1 = acc[mt][nt][1] * oscale;
            float v2 = acc[mt][nt][2] * oscale, v3 = acc[mt][nt][3] * oscale;
            if (bias) {
                v0 += bias[c]; v1 += bias[c + 1];
                v2 += bias[c]; v3 += bias[c + 1];
            }
            if (res) {
                v0 += res[(size_t)r0 * DD + c];
                v1 += res[(size_t)r0 * DD + c + 1];
                v2 += res[(size_t)(r0 + 8) * DD + c];
                v3 += res[(size_t)(r0 + 8) * DD + c + 1];
            }
            if (Cb) {
                *(uint32_t*)(Cb + (size_t)r0 * DD + c) = pack2(v0, v1);
                *(uint32_t*)(Cb + (size_t)(r0 + 8) * DD + c) = pack2(v2, v3);
            } else {
                Cf[(size_t)r0 * DD + c] = v0;
                Cf[(size_t)r0 * DD + c + 1] = v1;
                Cf[(size_t)(r0 + 8) * DD + c] = v2;
                Cf[(size_t)(r0 + 8) * DD + c + 1] = v3;
            }
        }
    }
}

// All 6 input projections. Rows 0..4095 = x, 4096..8191 = y.
// z=0 (Q) outputs are pre-scaled by LOG2E/16 (softmax scale folded in).
// z=2 (V) writes directly into transposed layout vT[b][h][dh][s].
__global__ __launch_bounds__(256, 2) void proj_kernel(
    const bf16* __restrict__ xb, const bf16* __restrict__ yb,
    const bf16* __restrict__ WqT, const bf16* __restrict__ WkT,
    const bf16* __restrict__ WvT,
    bf16* __restrict__ qx, bf16* __restrict__ kx,
    bf16* __restrict__ qy, bf16* __restrict__ ky,
    bf16* __restrict__ vxT, bf16* __restrict__ vyT)
{
    extern __shared__ char sm[];
    const int z = blockIdx.z;
    const int row0g = blockIdx.y * 128;
    const bool isx = (row0g < MM);
    const int row0 = isx ? row0g : row0g - MM;
    const bf16* A = isx ? xb : yb;
    const bf16* W = (z == 0) ? WqT : (z == 1) ? WkT : WvT;
    if (z == 2) {
        gemm_core(A, W, nullptr, nullptr, nullptr, nullptr,
                  isx ? vxT : vyT, row0, blockIdx.x * 128, sm, 1.0f);
    } else {
        bf16* C = (z == 0) ? (isx ? qy : qx) : (isx ? kx : ky);  // q cross-wired
        const float sc = (z == 0) ? QSCALE : 1.0f;
        gemm_core(A, W, nullptr, nullptr, nullptr, C, nullptr,
                  row0, blockIdx.x * 128, sm, sc);
    }
}

__global__ __launch_bounds__(256, 2) void out_kernel(
    const bf16* __restrict__ a1, const bf16* __restrict__ a2,
    const bf16* __restrict__ WoxT, const bf16* __restrict__ WoyT,
    const float* __restrict__ box, const float* __restrict__ boy,
    const float* __restrict__ x, const float* __restrict__ y,
    float* __restrict__ out)
{
    extern __shared__ char sm[];
    const int z = blockIdx.z;
    gemm_core(z ? a2 : a1, z ? WoyT : WoxT, z ? boy : box, z ? y : x,
              out + (size_t)z * MSZ, nullptr, nullptr,
              blockIdx.y * 128, blockIdx.x * 128, sm, 1.0f);
}

// ---------------------------------------------------------------------------
// Fused dual-stream flash attention: 256 q-rows / CTA, 256 thr / 8 warps,
// warp tile m=32, JT=64 keys/iter, register-resident P, static softmax.
// Q pre-scaled by LOG2E/16 at projection time -> exp2f(s) directly.
// lr sums unrounded p floats (tree FADD, no bf16 unpack).
// ---------------------------------------------------------------------------
#define QST 136                      // Q/K row stride (128 concat + 8)
#define VST 72                       // V row stride (64 keys + 8)
#define AJT 64                       // keys per iteration
#define AQE (256*QST)                // 34816 elems
#define AKE (64*QST)                 // 8704 elems (K stage)
#define AVE (64*VST)                 // 4608 elems per V stream
#define ASTG (AKE + 2*AVE)           // 17920 elems per stage
#define ATTN_SMEM_BYTES ((AQE + 2*ASTG)*2)   // 141312

__global__ __launch_bounds__(256, 1) void attn_tc(
    const bf16* __restrict__ qx, const bf16* __restrict__ kx, const bf16* __restrict__ vxT,
    const bf16* __restrict__ qy, const bf16* __restrict__ ky, const bf16* __restrict__ vyT,
    bf16* __restrict__ a1o, bf16* __restrict__ a2o)
{
    extern __shared__ char shraw[];
    bf16* Qs = (bf16*)shraw;

    const int tid = threadIdx.x;
    const int lane = tid & 31;
    const int warp = tid >> 5;       // 0..7
    const int tq = lane >> 2;
    const int tr = lane & 3;
    const int m0 = warp * 32;        // warp's 32 q-rows

    // ldmatrix lane constants (byte offsets)
    const int sel = lane >> 3, rin = lane & 7;
    const int aCq  = ((m0 + (sel & 1) * 8 + rin) * QST + (sel >> 1) * 8) * 2;  // Q m-tile 0
    const int aCq2 = aCq + 16 * QST * 2;                                       // Q m-tile 1
    const int bCk = (((sel >> 1) * 8 + rin) * QST + (sel & 1) * 8) * 2;        // K B-frag
    const int bCv = (((sel >> 1) * 8 + rin) * VST + (sel & 1) * 8) * 2;        // V B-frag

    const int bh = blockIdx.y;
    const int b = bh >> 4;
    const int h = bh & 15;
    const int q0 = blockIdx.x * 256;
    const size_t base = ((size_t)b * SS) * DD + (size_t)h * DH;
    const size_t vtb = (size_t)bh * DH * SS;

    auto kv_prefetch = [&](int j0, int stg) {
        bf16* Kb = Qs + AQE + stg * ASTG;
        bf16* Vxs = Kb + AKE;
        bf16* Vys = Vxs + AVE;
#pragma unroll
        for (int i = 0; i < 8; i++) {
            const int c = tid + i * 256;   // 0..2047
            if (c < 1024) {
                // K: 64 key-rows x 128 concat dims
                const int row = c >> 4;
                const int half = (c >> 3) & 1;
                const int j = c & 7;
                const bf16* src = (half ? ky : kx) + base + (size_t)(j0 + row) * DD + j * 8;
                CP16(s2u(Kb + row * QST + half * 64 + j * 8), src);
            } else {
                // V: 2 streams x 64 dh-rows x 64 keys
                const int c2 = c - 1024;
                const int t = c2 >> 9;
                const int r = (c2 >> 3) & 63;
                const int j = c2 & 7;
                const bf16* src = (t ? vyT : vxT) + vtb + (size_t)r * SS + j0 + j * 8;
                CP16(s2u((t ? Vys : Vxs) + r * VST + j * 8), src);
            }
        }
        CP_COMMIT();
    };

    // prologue: Q (256 rows x 128 concat) + stage 0
#pragma unroll
    for (int i = 0; i < 16; i++) {
        const int c = tid + i * 256;   // 0..4095
        const int row = c >> 4;
        const int half = (c >> 3) & 1;
        const int j = c & 7;
        const bf16* src = (half ? qy : qx) + base + (size_t)(q0 + row) * DD + j * 8;
        CP16(s2u(Qs + row * QST + half * 64 + j * 8), src);
    }
    CP_COMMIT();
    kv_prefetch(0, 0);

    const uint32_t qsu = s2u(Qs);

    float lr[2][2] = {{0.f, 0.f}, {0.f, 0.f}};   // [m-tile][row-half] partial sums
    float acc1[2][8][4], acc2[2][8][4];
#pragma unroll
    for (int mf = 0; mf < 2; mf++)
#pragma unroll
        for (int nt = 0; nt < 8; nt++)
#pragma unroll
            for (int i = 0; i < 4; i++) { acc1[mf][nt][i] = 0.f; acc2[mf][nt][i] = 0.f; }

    for (int jn = 0; jn < SS / AJT; jn++) {
        CP_WAIT(0);
        __syncthreads();
        if (jn + 1 < SS / AJT) kv_prefetch((jn + 1) * AJT, (jn + 1) & 1);

        bf16* Kb = Qs + AQE + (jn & 1) * ASTG;
        const uint32_t ksu = s2u(Kb);
        const uint32_t vxsu = s2u(Kb + AKE);
        const uint32_t vysu = s2u(Kb + AKE + AVE);

        // ---- scores: S[32 x 64] over concat k=128 (Q pre-scaled) ----
        float s[2][8][4];
#pragma unroll
        for (int mf = 0; mf < 2; mf++)
#pragma unroll
            for (int nt = 0; nt < 8; nt++)
#pragma unroll
                for (int i = 0; i < 4; i++) s[mf][nt][i] = 0.f;

#pragma unroll
        for (int k0 = 0; k0 < 128; k0 += 16) {
            const int kb = k0 * 2;
            uint32_t a0[4], a1[4];
            LDSM4(a0, qsu + aCq + kb);
            LDSM4(a1, qsu + aCq2 + kb);
#pragma unroll
            for (int np = 0; np < 4; np++) {
                uint32_t bfr[4];
                LDSM4(bfr, ksu + bCk + np * (16 * QST * 2) + kb);
                mma_bf16(s[0][2 * np],     a0, bfr[0], bfr[1]);
                mma_bf16(s[0][2 * np + 1], a0, bfr[2], bfr[3]);
                mma_bf16(s[1][2 * np],     a1, bfr[0], bfr[1]);
                mma_bf16(s[1][2 * np + 1], a1, bfr[2], bfr[3]);
            }
        }

        // ---- static softmax + pack P into PV A-fragments (registers) ----
        uint32_t pp[2][4][4];
#pragma unroll
        for (int mf = 0; mf < 2; mf++)
#pragma unroll
            for (int nt = 0; nt < 8; nt++) {
                const float p0 = exp2f(s[mf][nt][0]);
                const float p1 = exp2f(s[mf][nt][1]);
                const float p2 = exp2f(s[mf][nt][2]);
                const float p3 = exp2f(s[mf][nt][3]);
                lr[mf][0] += p0 + p1;
                lr[mf][1] += p2 + p3;
                bf162 h01 = __floats2bfloat162_rn(p0, p1);
                bf162 h23 = __floats2bfloat162_rn(p2, p3);
                pp[mf][nt >> 1][(nt & 1) * 2 + 0] = *reinterpret_cast<uint32_t*>(&h01);
                pp[mf][nt >> 1][(nt & 1) * 2 + 1] = *reinterpret_cast<uint32_t*>(&h23);
            }

        // ---- PV: acc1 += P@Vx^T, acc2 += P@Vy^T (k = 64 keys, 4 blocks) ----
#pragma unroll
        for (int kb4 = 0; kb4 < 4; kb4++) {
            const int kb = kb4 * 32;   // 16 keys = 32 bytes
#pragma unroll
            for (int np = 0; np < 4; np++) {
                uint32_t bx[4], by[4];
                LDSM4(bx, vxsu + bCv + np * (16 * VST * 2) + kb);
                mma_bf16(acc1[0][2 * np],     pp[0][kb4], bx[0], bx[1]);
                mma_bf16(acc1[0][2 * np + 1], pp[0][kb4], bx[2], bx[3]);
                mma_bf16(acc1[1][2 * np],     pp[1][kb4], bx[0], bx[1]);
                mma_bf16(acc1[1][2 * np + 1], pp[1][kb4], bx[2], bx[3]);
                LDSM4(by, vysu + bCv + np * (16 * VST * 2) + kb);
                mma_bf16(acc2[0][2 * np],     pp[0][kb4], by[0], by[1]);
                mma_bf16(acc2[0][2 * np + 1], pp[0][kb4], by[2], by[3]);
                mma_bf16(acc2[1][2 * np],     pp[1][kb4], by[0], by[1]);
                mma_bf16(acc2[1][2 * np + 1], pp[1][kb4], by[2], by[3]);
            }
        }
    }

    // ---- final l reduction across the 4 lanes sharing each row ----
#pragma unroll
    for (int mf = 0; mf < 2; mf++) {
#pragma unroll
        for (int r = 0; r < 2; r++) {
            lr[mf][r] += __shfl_xor_sync(0xffffffffu, lr[mf][r], 1);
            lr[mf][r] += __shfl_xor_sync(0xffffffffu, lr[mf][r], 2);
        }
    }

    // ---- normalize + write bf16 ----
#pragma unroll
    for (int mf = 0; mf < 2; mf++) {
        const float inv0 = 1.0f / lr[mf][0];
        const float inv1 = 1.0f / lr[mf][1];
        const size_t r0g = base + (size_t)(q0 + m0 + mf * 16 + tq) * DD;
        const size_t r1g = base + (size_t)(q0 + m0 + mf * 16 + tq + 8) * DD;
#pragma unroll
        for (int nt = 0; nt < 8; nt++) {
            const int c = nt * 8 + 2 * tr;
            *(uint32_t*)(a1o + r0g + c) = pack2(acc1[mf][nt][0] * inv0, acc1[mf][nt][1] * inv0);
            *(uint32_t*)(a1o + r1g + c) = pack2(acc1[mf][nt][2] * inv1, acc1[mf][nt][3] * inv1);
            *(uint32_t*)(a2o + r0g + c) = pack2(acc2[mf][nt][0] * inv0, acc2[mf][nt][1] * inv0);
            *(uint32_t*)(a2o + r1g + c) = pack2(acc2[mf][nt][2] * inv1, acc2[mf][nt][3] * inv1);
        }
    }
}

// ---------------------------------------------------------------------------
// Launch
// ---------------------------------------------------------------------------
extern "C" void kernel_launch(void* const* d_in, const int* in_sizes, int n_in,
                              void* d_out, int out_size)
{
    const float* x   = (const float*)d_in[0];
    const float* y   = (const float*)d_in[1];
    const float* Wq  = (const float*)d_in[2];
    const float* Wk  = (const float*)d_in[3];
    const float* Wv  = (const float*)d_in[4];
    const float* Wox = (const float*)d_in[5];
    const float* box = (const float*)d_in[6];
    const float* Woy = (const float*)d_in[7];
    const float* boy = (const float*)d_in[8];
    float* out = (float*)d_out;

    void* p;
    bf16 *xb, *yb, *WqT, *WkT, *WvT, *WoxT, *WoyT;
    bf16 *qx, *kx, *qy, *ky, *vxT, *vyT, *a1, *a2;
    cudaGetSymbolAddress(&p, g_xb);  xb  = (bf16*)p;
    cudaGetSymbolAddress(&p, g_yb);  yb  = (bf16*)p;
    cudaGetSymbolAddress(&p, g_WqT); WqT = (bf16*)p;
    cudaGetSymbolAddress(&p, g_WkT); WkT = (bf16*)p;
    cudaGetSymbolAddress(&p, g_WvT); WvT = (bf16*)p;
    cudaGetSymbolAddress(&p, g_WoxT); WoxT = (bf16*)p;
    cudaGetSymbolAddress(&p, g_WoyT); WoyT = (bf16*)p;
    cudaGetSymbolAddress(&p, g_qx);  qx = (bf16*)p;
    cudaGetSymbolAddress(&p, g_kx);  kx = (bf16*)p;
    cudaGetSymbolAddress(&p, g_qy);  qy = (bf16*)p;
    cudaGetSymbolAddress(&p, g_ky);  ky = (bf16*)p;
    cudaGetSymbolAddress(&p, g_vxT); vxT = (bf16*)p;
    cudaGetSymbolAddress(&p, g_vyT); vyT = (bf16*)p;
    cudaGetSymbolAddress(&p, g_a1);  a1 = (bf16*)p;
    cudaGetSymbolAddress(&p, g_a2);  a2 = (bf16*)p;

    cudaFuncSetAttribute(proj_kernel, cudaFuncAttributeMaxDynamicSharedMemorySize,
                         GEMM_SMEM_BYTES);
    cudaFuncSetAttribute(out_kernel, cudaFuncAttributeMaxDynamicSharedMemorySize,
                         GEMM_SMEM_BYTES);
    cudaFuncSetAttribute(attn_tc, cudaFuncAttributeMaxDynamicSharedMemorySize,
                         ATTN_SMEM_BYTES);

    convxy<<<dim3(MSZ / 1024, 2), 256>>>(x, y, xb, yb);
    wconv<<<dim3(32, 32, 5), 256>>>(Wq, Wk, Wv, Wox, Woy, WqT, WkT, WvT, WoxT, WoyT);

    proj_kernel<<<dim3(DD / 128, 2 * MM / 128, 3), 256, GEMM_SMEM_BYTES>>>(
        xb, yb, WqT, WkT, WvT, qx, kx, qy, ky, vxT, vyT);

    attn_tc<<<dim3(SS / 256, BB * HH), 256, ATTN_SMEM_BYTES>>>(
        qx, kx, vxT, qy, ky, vyT, a1, a2);

    out_kernel<<<dim3(DD / 128, MM / 128, 2), 256, GEMM_SMEM_BYTES>>>(
        a1, a2, WoxT, WoyT, box, boy, x, y, out);
}